// round 11
// baseline (speedup 1.0000x reference)
#include <cuda_runtime.h>
#include <cuda_bf16.h>
#include <cstdint>

// ===================== scratch (static device arrays; no allocs) ============
__device__ __nv_bfloat16  g_xhi[262144ull * 256];          // X split hi/lo
__device__ __nv_bfloat16  g_xlo[262144ull * 256];
__device__ __nv_bfloat16  g_qh[262144ull * 256];           // Q (scaled+bias) hi/lo
__device__ __nv_bfloat16  g_ql[262144ull * 256];
__device__ __nv_bfloat16  g_kh[262144ull * 256];           // K hi/lo
__device__ __nv_bfloat16  g_kl[262144ull * 256];
__device__ __nv_bfloat16  g_vth[4096ull * 256 * 64];       // V^T per window [d][j]
__device__ __nv_bfloat16  g_vtl[4096ull * 256 * 64];
__device__ __nv_bfloat16  g_ohi[262144ull * 256];          // attn out hi/lo
__device__ __nv_bfloat16  g_olo[262144ull * 256];
__device__ __nv_bfloat16  g_wqkv_hi[768 * 256];            // W^T [n][k]
__device__ __nv_bfloat16  g_wqkv_lo[768 * 256];
__device__ __nv_bfloat16  g_wproj_hi[256 * 256];
__device__ __nv_bfloat16  g_wproj_lo[256 * 256];

// ===================== helpers ==============================================
__device__ __forceinline__ uint32_t smem_to_u32(const void* p) {
    uint32_t a;
    asm("{ .reg .u64 t; cvta.to.shared.u64 t, %1; cvt.u32.u64 %0, t; }"
        : "=r"(a) : "l"(p));
    return a;
}
__device__ __forceinline__ void ldsm4(uint32_t (&r)[4], uint32_t addr) {
    asm volatile("ldmatrix.sync.aligned.m8n8.x4.shared.b16 {%0,%1,%2,%3}, [%4];"
                 : "=r"(r[0]), "=r"(r[1]), "=r"(r[2]), "=r"(r[3]) : "r"(addr));
}
__device__ __forceinline__ void mma16816(float (&d)[4], const uint32_t (&a)[4],
                                         uint32_t b0, uint32_t b1) {
    asm volatile("mma.sync.aligned.m16n8k16.row.col.f32.bf16.bf16.f32 "
                 "{%0,%1,%2,%3}, {%4,%5,%6,%7}, {%8,%9}, {%0,%1,%2,%3};"
                 : "+f"(d[0]), "+f"(d[1]), "+f"(d[2]), "+f"(d[3])
                 : "r"(a[0]), "r"(a[1]), "r"(a[2]), "r"(a[3]), "r"(b0), "r"(b1));
}
__device__ __forceinline__ void split2(float x, float y,
                                       __nv_bfloat162& h, __nv_bfloat162& l) {
    h.x = __float2bfloat16(x); h.y = __float2bfloat16(y);
    l.x = __float2bfloat16(x - __bfloat162float(h.x));
    l.y = __float2bfloat16(y - __bfloat162float(h.y));
}
#define CP16(dst, src) \
    asm volatile("cp.async.cg.shared.global [%0], [%1], 16;" \
        :: "r"((uint32_t)(dst)), "l"(__cvta_generic_to_global((const void*)(src))) : "memory")
#define CP_COMMIT() asm volatile("cp.async.commit_group;" ::: "memory")
#define CP_WAIT(n)  asm volatile("cp.async.wait_group %0;" :: "n"(n) : "memory")

// ===================== prep kernels =========================================
__global__ void __launch_bounds__(1024) split_x_kernel(const float* __restrict__ x) {
    size_t idx = (size_t)blockIdx.x * 1024 + threadIdx.x;  // float4 index
    float4 v = ((const float4*)x)[idx];
    __nv_bfloat162 h0, h1, l0, l1;
    split2(v.x, v.y, h0, l0);
    split2(v.z, v.w, h1, l1);
    ((__nv_bfloat162*)g_xhi)[idx * 2]     = h0;
    ((__nv_bfloat162*)g_xhi)[idx * 2 + 1] = h1;
    ((__nv_bfloat162*)g_xlo)[idx * 2]     = l0;
    ((__nv_bfloat162*)g_xlo)[idx * 2 + 1] = l1;
}

__global__ void __launch_bounds__(512) split_w_kernel(const float* __restrict__ qkv_w,
                                                      const float* __restrict__ proj_w) {
    int idx = blockIdx.x * 512 + threadIdx.x;
    float v; __nv_bfloat16 *ph, *pl; int off;
    if (idx < 196608) {
        int n = idx >> 8, k = idx & 255;
        v = qkv_w[k * 768 + n];
        ph = g_wqkv_hi; pl = g_wqkv_lo; off = n * 256 + k;
    } else {
        int j = idx - 196608;
        int n = j >> 8, k = j & 255;
        v = proj_w[k * 256 + n];
        ph = g_wproj_hi; pl = g_wproj_lo; off = n * 256 + k;
    }
    __nv_bfloat16 h = __float2bfloat16(v);
    ph[off] = h;
    pl[off] = __float2bfloat16(v - __bfloat162float(h));
}

// ===================== split-bf16 HMMA GEMM (k16 x 4-stage, 64x64 warps) ====
// CTA tile 128m x 256n, K=256 in 16 chunks of 16. 8 warps (2m x 4n), warp
// tile 64x64. smem rows stride 48B (16 bf16 + pad) -> ldsm conflict-free.
// MODE 0: A=X hi/lo, W=qkv^T; blockIdx.x in {0,1,2} selects Q/K/V epilogue.
// MODE 1: A=O hi/lo, W=proj^T; fp32 out.
#define GA_H 0
#define GA_L 6144
#define GB_H 12288
#define GB_L 24576
#define GSTAGE 36864
#define GNSTAGE 4
#define GEMM_SMEM (GNSTAGE * GSTAGE)       // 147456

template<int MODE>
__global__ void __launch_bounds__(256, 1)
gemm_mma_kernel(const float* __restrict__ bias, float* __restrict__ Cext)
{
    extern __shared__ unsigned char smg[];
    const __nv_bfloat16* Ahi = (MODE == 0) ? g_xhi : g_ohi;
    const __nv_bfloat16* Alo = (MODE == 0) ? g_xlo : g_olo;
    const __nv_bfloat16* Whi = (MODE == 0) ? g_wqkv_hi : g_wproj_hi;
    const __nv_bfloat16* Wlo = (MODE == 0) ? g_wqkv_lo : g_wproj_lo;

    const int tid  = threadIdx.x;
    const int lane = tid & 31;
    const int wid  = tid >> 5;
    const int m0   = blockIdx.y * 128;
    const int nsel = blockIdx.x;           // MODE0: 0=Q 1=K 2=V
    const int n0   = nsel * 256;
    const int wm   = (wid & 1) * 64;
    const int wn   = (wid >> 1) * 64;
    const uint32_t sb = smem_to_u32(smg);

    float acc[4][8][4];
#pragma unroll
    for (int a = 0; a < 4; ++a)
#pragma unroll
        for (int b = 0; b < 8; ++b)
#pragma unroll
            for (int c = 0; c < 4; ++c) acc[a][b][c] = 0.0f;

    const int arow = (lane & 7) + ((lane >> 3) & 1) * 8;
    const int kqof = (lane >> 4) * 8;

    auto load_stage = [&](int kc) {
        const int kb = kc * 16;
        const uint32_t base = sb + (kc & (GNSTAGE - 1)) * GSTAGE;
        {   // A: 128 rows x 16k -> 256 int4 per array
            int row = tid >> 1, kq = tid & 1;
            size_t go = (size_t)(m0 + row) * 256 + kb + kq * 8;
            uint32_t so = (uint32_t)(row * 48 + kq * 16);
            CP16(base + GA_H + so, Ahi + go);
            CP16(base + GA_L + so, Alo + go);
        }
#pragma unroll
        for (int it = 0; it < 2; ++it) {   // B: 256 rows -> 512 int4 per array
            int e = tid + it * 256;
            int row = e >> 1, kq = e & 1;
            size_t go = (size_t)(n0 + row) * 256 + kb + kq * 8;
            uint32_t so = (uint32_t)(row * 48 + kq * 16);
            CP16(base + GB_H + so, Whi + go);
            CP16(base + GB_L + so, Wlo + go);
        }
    };

#pragma unroll
    for (int s = 0; s < GNSTAGE - 1; ++s) {
        load_stage(s);
        CP_COMMIT();
    }

    for (int kc = 0; kc < 16; ++kc) {
        CP_WAIT(GNSTAGE - 2);
        __syncthreads();
        if (kc + GNSTAGE - 1 < 16) load_stage(kc + GNSTAGE - 1);
        CP_COMMIT();                        // empty commits in tail keep counts

        const uint32_t base = sb + (kc & (GNSTAGE - 1)) * GSTAGE;
        uint32_t ah[4][4], al[4][4];
#pragma unroll
        for (int mf = 0; mf < 4; ++mf) {
            uint32_t ad = base + (uint32_t)((wm + mf * 16 + arow) * 48 + kqof * 2);
            ldsm4(ah[mf], ad + GA_H);
            ldsm4(al[mf], ad + GA_L);
        }
#pragma unroll
        for (int np = 0; np < 4; ++np) {
            uint32_t bd = base + (uint32_t)((wn + np * 16 + arow) * 48 + kqof * 2);
            uint32_t bh[4], bl[4];
            ldsm4(bh, bd + GB_H);
            ldsm4(bl, bd + GB_L);
#pragma unroll
            for (int mf = 0; mf < 4; ++mf)
#pragma unroll
                for (int nf = 0; nf < 2; ++nf) {
                    float (&d)[4] = acc[mf][np * 2 + nf];
                    mma16816(d, ah[mf], bh[nf], bh[nf + 2]);
                    mma16816(d, ah[mf], bl[nf], bl[nf + 2]);
                    mma16816(d, al[mf], bh[nf], bh[nf + 2]);
                }
        }
    }

    // epilogue
    const int g   = lane >> 2;
    const int tg2 = (lane & 3) * 2;
#pragma unroll
    for (int mf = 0; mf < 4; ++mf) {
        const int row = m0 + wm + mf * 16 + g;      // rows row, row+8
#pragma unroll
        for (int f = 0; f < 8; ++f) {
            const int cl = wn + (f >> 1) * 16 + (f & 1) * 8 + tg2;  // 0..255
            float bx = __ldg(&bias[n0 + cl]);
            float by = __ldg(&bias[n0 + cl + 1]);
            float v0 = acc[mf][f][0] + bx, v1 = acc[mf][f][1] + by;  // row
            float v2 = acc[mf][f][2] + bx, v3 = acc[mf][f][3] + by;  // row+8
            if (MODE == 1) {
                *(float2*)&Cext[(size_t)row * 256 + cl]       = make_float2(v0, v1);
                *(float2*)&Cext[(size_t)(row + 8) * 256 + cl] = make_float2(v2, v3);
            } else if (nsel == 0) {                 // Q: scale 1/16, split
                v0 *= 0.0625f; v1 *= 0.0625f; v2 *= 0.0625f; v3 *= 0.0625f;
                __nv_bfloat162 h, l;
                split2(v0, v1, h, l);
                *(__nv_bfloat162*)&g_qh[(size_t)row * 256 + cl] = h;
                *(__nv_bfloat162*)&g_ql[(size_t)row * 256 + cl] = l;
                split2(v2, v3, h, l);
                *(__nv_bfloat162*)&g_qh[(size_t)(row + 8) * 256 + cl] = h;
                *(__nv_bfloat162*)&g_ql[(size_t)(row + 8) * 256 + cl] = l;
            } else if (nsel == 1) {                 // K: split
                __nv_bfloat162 h, l;
                split2(v0, v1, h, l);
                *(__nv_bfloat162*)&g_kh[(size_t)row * 256 + cl] = h;
                *(__nv_bfloat162*)&g_kl[(size_t)row * 256 + cl] = l;
                split2(v2, v3, h, l);
                *(__nv_bfloat162*)&g_kh[(size_t)(row + 8) * 256 + cl] = h;
                *(__nv_bfloat162*)&g_kl[(size_t)(row + 8) * 256 + cl] = l;
            } else {                                // V: split + transpose per window
#pragma unroll
                for (int rr = 0; rr < 2; ++rr) {
                    int r  = row + rr * 8;
                    float a0 = rr ? v2 : v0, a1 = rr ? v3 : v1;
                    size_t base2 = ((size_t)(r >> 6) * 256) * 64 + (r & 63);
                    __nv_bfloat16 h0 = __float2bfloat16(a0);
                    __nv_bfloat16 h1 = __float2bfloat16(a1);
                    g_vth[base2 + (size_t)cl * 64]       = h0;
                    g_vth[base2 + (size_t)(cl + 1) * 64] = h1;
                    g_vtl[base2 + (size_t)cl * 64] =
                        __float2bfloat16(a0 - __bfloat162float(h0));
                    g_vtl[base2 + (size_t)(cl + 1) * 64] =
                        __float2bfloat16(a1 - __bfloat162float(h1));
                }
            }
        }
    }
}

// ===================== attention (mma.sync, 512 threads) =====================
// smem bytes: Qh/Ql, Kh/Kl: 64 rows x 528B; Vt h/l: 256 rows x 144B;
// P h/l: 64 rows x 144B; reductions (4 segments) + bias tables.
#define AQ_H   0
#define AQ_L   33792
#define AK_H   67584
#define AK_L   101376
#define AVT_H  135168
#define AVT_L  172032
#define AP_H   208896
#define AP_L   218112
#define A_RED  227328      // pmax[4][64] floats, psum[4][64] floats
#define A_TAB  229376      // phi[0..14] @ +0, th[0..14] @ +16 floats
#define ATTN_SMEM 229504

__global__ void __launch_bounds__(512, 1)
attn_kernel(const float* __restrict__ theta_max,
            const float* __restrict__ a_p, const float* __restrict__ b_p,
            const float* __restrict__ a_r, const float* __restrict__ b_r)
{
    extern __shared__ unsigned char sm[];
    const uint32_t sb = smem_to_u32(sm);
    float* pmax = (float*)(sm + A_RED);        // [4][64]
    float* psum = pmax + 256;                  // [4][64]
    float* tabf = (float*)(sm + A_TAB);

    const int tid  = threadIdx.x;
    const int lane = tid & 31;
    const int wid  = tid >> 5;
    const int w    = blockIdx.x;

    // async tile loads: group0 = Q,K; group1 = Vt
    {
        const int4* qh = (const int4*)(g_qh + (size_t)w * 64 * 256);
        const int4* ql = (const int4*)(g_ql + (size_t)w * 64 * 256);
        const int4* kh = (const int4*)(g_kh + (size_t)w * 64 * 256);
        const int4* kl = (const int4*)(g_kl + (size_t)w * 64 * 256);
        const int4* vh = (const int4*)(g_vth + (size_t)w * 256 * 64);
        const int4* vl = (const int4*)(g_vtl + (size_t)w * 256 * 64);
#pragma unroll
        for (int it = 0; it < 4; ++it) {
            int e = tid + it * 512;            // 0..2047
            uint32_t so = (uint32_t)((e >> 5) * 528 + (e & 31) * 16);
            CP16(sb + AQ_H + so, qh + e);
            CP16(sb + AQ_L + so, ql + e);
            CP16(sb + AK_H + so, kh + e);
            CP16(sb + AK_L + so, kl + e);
        }
        CP_COMMIT();
#pragma unroll
        for (int it = 0; it < 4; ++it) {
            int e = tid + it * 512;
            uint32_t sv = (uint32_t)((e >> 3) * 144 + (e & 7) * 16);
            CP16(sb + AVT_H + sv, vh + e);
            CP16(sb + AVT_L + sv, vl + e);
        }
        CP_COMMIT();
    }

    // bias tables: phi[dx+7] @ tabf[0..14], th[dy+7] @ tabf[16..30]
    if (tid < 15) {
        int dx = tid - 7;
        int ai = dx < 0 ? dx + 15 : dx;
        float s, c;
        sincosf((float)dx * (6.283185307179586f / 64.0f), &s, &c);
        tabf[tid] = __ldg(&a_p[ai]) * c + __ldg(&b_p[ai]) * s;
    } else if (tid >= 16 && tid < 31) {
        int dy = tid - 16 - 7;
        int ri = dy < 0 ? dy + 15 : dy;
        float tm = __ldg(&theta_max[w >> 6]);
        float s, c;
        sincosf((float)dy * (tm * 0.015625f), &s, &c);
        tabf[tid] = __ldg(&a_r[ri]) * c + __ldg(&b_r[ri]) * s;
    }

    CP_WAIT(1);                                // Q,K in smem
    __syncthreads();

    const int wm   = (wid & 3) * 16;
    const int wn2  = wid >> 2;                 // 0..3
    const int arow = (lane & 7) + ((lane >> 3) & 1) * 8;
    const int kqof = (lane >> 4) * 8;
    const int g    = lane >> 2;
    const int tg2  = (lane & 3) * 2;

    // ---- S = Q @ K^T (3-term split), warp tile 16m x 16n ----
    float accS[2][4];
#pragma unroll
    for (int f = 0; f < 2; ++f)
#pragma unroll
        for (int c = 0; c < 4; ++c) accS[f][c] = 0.0f;

#pragma unroll
    for (int kk = 0; kk < 16; ++kk) {
        const int kcol = kk * 16 + kqof;
        uint32_t aoff = (uint32_t)((wm + arow) * 528 + kcol * 2);
        uint32_t ah[4], al[4];
        ldsm4(ah, sb + AQ_H + aoff);
        ldsm4(al, sb + AQ_L + aoff);
        uint32_t boff = (uint32_t)((wn2 * 16 + arow) * 528 + kcol * 2);
        uint32_t bh[4], bl[4];
        ldsm4(bh, sb + AK_H + boff);
        ldsm4(bl, sb + AK_L + boff);
#pragma unroll
        for (int nf = 0; nf < 2; ++nf) {
            float (&d)[4] = accS[nf];
            mma16816(d, ah, bh[nf], bh[nf + 2]);
            mma16816(d, ah, bl[nf], bl[nf + 2]);
            mma16816(d, al, bh[nf], bh[nf + 2]);
        }
    }

    // ---- bias + softmax (rows i0, i1; 16-wide segment per warp) ----
    const int i0 = wm + g, i1 = i0 + 8;
    float m0v = -1e30f, m1v = -1e30f;
#pragma unroll
    for (int f = 0; f < 2; ++f) {
        int jb = wn2 * 16 + f * 8 + tg2;
#pragma unroll
        for (int e = 0; e < 2; ++e) {
            int j   = jb + e;
            int dxi = (i0 & 7) - (j & 7) + 7;
            int dyi = (i0 >> 3) - (j >> 3) + 7;
            float phi = tabf[dxi];
            accS[f][e]     += phi + tabf[16 + dyi];
            accS[f][2 + e] += phi + tabf[16 + dyi + 1];
            m0v = fmaxf(m0v, accS[f][e]);
            m1v = fmaxf(m1v, accS[f][2 + e]);
        }
    }
    m0v = fmaxf(m0v, __shfl_xor_sync(0xffffffffu, m0v, 1));
    m0v = fmaxf(m0v, __shfl_xor_sync(0xffffffffu, m0v, 2));
    m1v = fmaxf(m1v, __shfl_xor_sync(0xffffffffu, m1v, 1));
    m1v = fmaxf(m1v, __shfl_xor_sync(0xffffffffu, m1v, 2));
    pmax[wn2 * 64 + i0] = m0v;
    pmax[wn2 * 64 + i1] = m1v;
    __syncthreads();
    const float mx0 = fmaxf(fmaxf(pmax[i0], pmax[64 + i0]),
                            fmaxf(pmax[128 + i0], pmax[192 + i0]));
    const float mx1 = fmaxf(fmaxf(pmax[i1], pmax[64 + i1]),
                            fmaxf(pmax[128 + i1], pmax[192 + i1]));

    float s0 = 0.0f, s1 = 0.0f;
#pragma unroll
    for (int f = 0; f < 2; ++f)
#pragma unroll
        for (int e = 0; e < 2; ++e) {
            accS[f][e]     = __expf(accS[f][e]     - mx0);
            accS[f][2 + e] = __expf(accS[f][2 + e] - mx1);
            s0 += accS[f][e];
            s1 += accS[f][2 + e];
        }
    s0 += __shfl_xor_sync(0xffffffffu, s0, 1);
    s0 += __shfl_xor_sync(0xffffffffu, s0, 2);
    s1 += __shfl_xor_sync(0xffffffffu, s1, 1);
    s1 += __shfl_xor_sync(0xffffffffu, s1, 2);
    psum[wn2 * 64 + i0] = s0;
    psum[wn2 * 64 + i1] = s1;
    __syncthreads();
    const float inv0 = 1.0f / (psum[i0] + psum[64 + i0] + psum[128 + i0] + psum[192 + i0]);
    const float inv1 = 1.0f / (psum[i1] + psum[64 + i1] + psum[128 + i1] + psum[192 + i1]);

    // store P hi/lo (bf16) to smem
#pragma unroll
    for (int f = 0; f < 2; ++f) {
        int jb = wn2 * 16 + f * 8 + tg2;
        __nv_bfloat162 h, l;
        split2(accS[f][0] * inv0, accS[f][1] * inv0, h, l);
        *(__nv_bfloat162*)(sm + AP_H + i0 * 144 + jb * 2) = h;
        *(__nv_bfloat162*)(sm + AP_L + i0 * 144 + jb * 2) = l;
        split2(accS[f][2] * inv1, accS[f][3] * inv1, h, l);
        *(__nv_bfloat162*)(sm + AP_H + i1 * 144 + jb * 2) = h;
        *(__nv_bfloat162*)(sm + AP_L + i1 * 144 + jb * 2) = l;
    }
    CP_WAIT(0);                                // Vt in smem
    __syncthreads();

    // ---- O = P @ V, warp tile 16m x 64d ----
    float accO[8][4];
#pragma unroll
    for (int f = 0; f < 8; ++f)
#pragma unroll
        for (int c = 0; c < 4; ++c) accO[f][c] = 0.0f;

#pragma unroll
    for (int kk = 0; kk < 4; ++kk) {
        const int kcol = kk * 16 + kqof;
        uint32_t aoff = (uint32_t)((wm + arow) * 144 + kcol * 2);
        uint32_t ah[4], al[4];
        ldsm4(ah, sb + AP_H + aoff);
        ldsm4(al, sb + AP_L + aoff);
#pragma unroll
        for (int np = 0; np < 4; ++np) {
            uint32_t boff = (uint32_t)((wn2 * 64 + np * 16 + arow) * 144 + kcol * 2);
            uint32_t bh[4], bl[4];
            ldsm4(bh, sb + AVT_H + boff);
            ldsm4(bl, sb + AVT_L + boff);
#pragma unroll
            for (int nf = 0; nf < 2; ++nf) {
                float (&d)[4] = accO[np * 2 + nf];
                mma16816(d, ah, bh[nf], bh[nf + 2]);
                mma16816(d, ah, bl[nf], bl[nf + 2]);
                mma16816(d, al, bh[nf], bh[nf + 2]);
            }
        }
    }

    // epilogue: split O -> g_ohi/g_olo [row][256]
    const size_t r0 = (size_t)w * 64 + i0;
    const size_t r1 = (size_t)w * 64 + i1;
#pragma unroll
    for (int f = 0; f < 8; ++f) {
        int d = wn2 * 64 + (f >> 1) * 16 + (f & 1) * 8 + tg2;
        __nv_bfloat162 h, l;
        split2(accO[f][0], accO[f][1], h, l);
        *(__nv_bfloat162*)&g_ohi[r0 * 256 + d] = h;
        *(__nv_bfloat162*)&g_olo[r0 * 256 + d] = l;
        split2(accO[f][2], accO[f][3], h, l);
        *(__nv_bfloat162*)&g_ohi[r1 * 256 + d] = h;
        *(__nv_bfloat162*)&g_olo[r1 * 256 + d] = l;
    }
}

// ===================== launch ================================================
extern "C" void kernel_launch(void* const* d_in, const int* in_sizes, int n_in,
                              void* d_out, int out_size)
{
    (void)in_sizes; (void)n_in; (void)out_size;
    const float* x         = (const float*)d_in[0];
    const float* theta_max = (const float*)d_in[1];
    const float* qkv_w     = (const float*)d_in[2];
    const float* qkv_b     = (const float*)d_in[3];
    const float* proj_w    = (const float*)d_in[4];
    const float* proj_b    = (const float*)d_in[5];
    const float* a_p       = (const float*)d_in[6];
    const float* b_p       = (const float*)d_in[7];
    const float* a_r       = (const float*)d_in[8];
    const float* b_r       = (const float*)d_in[9];
    float* out = (float*)d_out;

    cudaFuncSetAttribute(gemm_mma_kernel<0>,
                         cudaFuncAttributeMaxDynamicSharedMemorySize, GEMM_SMEM);
    cudaFuncSetAttribute(gemm_mma_kernel<1>,
                         cudaFuncAttributeMaxDynamicSharedMemorySize, GEMM_SMEM);
    cudaFuncSetAttribute(attn_kernel,
                         cudaFuncAttributeMaxDynamicSharedMemorySize, ATTN_SMEM);

    split_x_kernel<<<16384, 1024>>>(x);
    split_w_kernel<<<512, 512>>>(qkv_w, proj_w);
    gemm_mma_kernel<0><<<dim3(3, 2048), 256, GEMM_SMEM>>>(qkv_b, nullptr);
    attn_kernel<<<4096, 512, ATTN_SMEM>>>(theta_max, a_p, b_p, a_r, b_r);
    gemm_mma_kernel<1><<<dim3(1, 2048), 256, GEMM_SMEM>>>(proj_b, out);
}

// round 13
// speedup vs baseline: 1.0223x; 1.0223x over previous
#include <cuda_runtime.h>
#include <cuda_bf16.h>
#include <cstdint>

// ===================== scratch (static device arrays; no allocs) ============
__device__ __nv_bfloat16  g_xhi[262144ull * 256];          // X split hi/lo
__device__ __nv_bfloat16  g_xlo[262144ull * 256];
__device__ __nv_bfloat16  g_qh[262144ull * 256];           // Q (scaled+bias) hi/lo
__device__ __nv_bfloat16  g_ql[262144ull * 256];
__device__ __nv_bfloat16  g_kh[262144ull * 256];           // K hi/lo
__device__ __nv_bfloat16  g_kl[262144ull * 256];
__device__ __nv_bfloat16  g_vth[4096ull * 256 * 64];       // V^T per window [d][j]
__device__ __nv_bfloat16  g_vtl[4096ull * 256 * 64];
__device__ __nv_bfloat16  g_ohi[262144ull * 256];          // attn out hi/lo
__device__ __nv_bfloat16  g_olo[262144ull * 256];
__device__ __nv_bfloat16  g_wqkv_hi[768 * 256];            // W^T [n][k]
__device__ __nv_bfloat16  g_wqkv_lo[768 * 256];
__device__ __nv_bfloat16  g_wproj_hi[256 * 256];
__device__ __nv_bfloat16  g_wproj_lo[256 * 256];

// ===================== helpers ==============================================
__device__ __forceinline__ uint32_t smem_to_u32(const void* p) {
    uint32_t a;
    asm("{ .reg .u64 t; cvta.to.shared.u64 t, %1; cvt.u32.u64 %0, t; }"
        : "=r"(a) : "l"(p));
    return a;
}
__device__ __forceinline__ void ldsm4(uint32_t (&r)[4], uint32_t addr) {
    asm volatile("ldmatrix.sync.aligned.m8n8.x4.shared.b16 {%0,%1,%2,%3}, [%4];"
                 : "=r"(r[0]), "=r"(r[1]), "=r"(r[2]), "=r"(r[3]) : "r"(addr));
}
__device__ __forceinline__ void mma16816(float (&d)[4], const uint32_t (&a)[4],
                                         uint32_t b0, uint32_t b1) {
    asm volatile("mma.sync.aligned.m16n8k16.row.col.f32.bf16.bf16.f32 "
                 "{%0,%1,%2,%3}, {%4,%5,%6,%7}, {%8,%9}, {%0,%1,%2,%3};"
                 : "+f"(d[0]), "+f"(d[1]), "+f"(d[2]), "+f"(d[3])
                 : "r"(a[0]), "r"(a[1]), "r"(a[2]), "r"(a[3]), "r"(b0), "r"(b1));
}
__device__ __forceinline__ void split2(float x, float y,
                                       __nv_bfloat162& h, __nv_bfloat162& l) {
    h.x = __float2bfloat16(x); h.y = __float2bfloat16(y);
    l.x = __float2bfloat16(x - __bfloat162float(h.x));
    l.y = __float2bfloat16(y - __bfloat162float(h.y));
}
#define CP16(dst, src) \
    asm volatile("cp.async.cg.shared.global [%0], [%1], 16;" \
        :: "r"((uint32_t)(dst)), "l"(__cvta_generic_to_global((const void*)(src))) : "memory")
#define CP_COMMIT() asm volatile("cp.async.commit_group;" ::: "memory")
#define CP_WAIT(n)  asm volatile("cp.async.wait_group %0;" :: "n"(n) : "memory")

// ===================== prep kernels =========================================
__global__ void __launch_bounds__(1024) split_x_kernel(const float* __restrict__ x) {
    size_t idx = (size_t)blockIdx.x * 1024 + threadIdx.x;  // float4 index
    float4 v = ((const float4*)x)[idx];
    __nv_bfloat162 h0, h1, l0, l1;
    split2(v.x, v.y, h0, l0);
    split2(v.z, v.w, h1, l1);
    ((__nv_bfloat162*)g_xhi)[idx * 2]     = h0;
    ((__nv_bfloat162*)g_xhi)[idx * 2 + 1] = h1;
    ((__nv_bfloat162*)g_xlo)[idx * 2]     = l0;
    ((__nv_bfloat162*)g_xlo)[idx * 2 + 1] = l1;
}

__global__ void __launch_bounds__(512) split_w_kernel(const float* __restrict__ qkv_w,
                                                      const float* __restrict__ proj_w) {
    int idx = blockIdx.x * 512 + threadIdx.x;
    float v; __nv_bfloat16 *ph, *pl; int off;
    if (idx < 196608) {
        int n = idx >> 8, k = idx & 255;
        v = qkv_w[k * 768 + n];
        ph = g_wqkv_hi; pl = g_wqkv_lo; off = n * 256 + k;
    } else {
        int j = idx - 196608;
        int n = j >> 8, k = j & 255;
        v = proj_w[k * 256 + n];
        ph = g_wproj_hi; pl = g_wproj_lo; off = n * 256 + k;
    }
    __nv_bfloat16 h = __float2bfloat16(v);
    ph[off] = h;
    pl[off] = __float2bfloat16(v - __bfloat162float(h));
}

// ===================== split-bf16 HMMA GEMM (k16 x 4-stage, 64x64 warps) ====
// CTA tile 128m x 256n, K=256 in 16 chunks of 16. 8 warps (2m x 4n), warp
// tile 64x64. smem rows stride 48B -> ldsm conflict-free.
// Split terms issued TERM-MAJOR per np group: each accumulator is touched at
// mma i, i+8, i+16 (RAW distance 8) so 2 warps/SMSP suffice to keep the
// tensor pipe fed at 1 CTA/SM.
// MODE 0: A=X hi/lo, W=qkv^T; blockIdx.x in {0,1,2} selects Q/K/V epilogue.
// MODE 1: A=O hi/lo, W=proj^T; fp32 out.
#define GA_H 0
#define GA_L 6144
#define GB_H 12288
#define GB_L 24576
#define GSTAGE 36864
#define GNSTAGE 4
#define GEMM_SMEM (GNSTAGE * GSTAGE)       // 147456

template<int MODE>
__global__ void __launch_bounds__(256, 1)
gemm_mma_kernel(const float* __restrict__ bias, float* __restrict__ Cext)
{
    extern __shared__ unsigned char smg[];
    const __nv_bfloat16* Ahi = (MODE == 0) ? g_xhi : g_ohi;
    const __nv_bfloat16* Alo = (MODE == 0) ? g_xlo : g_olo;
    const __nv_bfloat16* Whi = (MODE == 0) ? g_wqkv_hi : g_wproj_hi;
    const __nv_bfloat16* Wlo = (MODE == 0) ? g_wqkv_lo : g_wproj_lo;

    const int tid  = threadIdx.x;
    const int lane = tid & 31;
    const int wid  = tid >> 5;
    const int m0   = blockIdx.y * 128;
    const int nsel = blockIdx.x;           // MODE0: 0=Q 1=K 2=V
    const int n0   = nsel * 256;
    const int wm   = (wid & 1) * 64;
    const int wn   = (wid >> 1) * 64;
    const uint32_t sb = smem_to_u32(smg);

    float acc[4][8][4];
#pragma unroll
    for (int a = 0; a < 4; ++a)
#pragma unroll
        for (int b = 0; b < 8; ++b)
#pragma unroll
            for (int c = 0; c < 4; ++c) acc[a][b][c] = 0.0f;

    const int arow = (lane & 7) + ((lane >> 3) & 1) * 8;
    const int kqof = (lane >> 4) * 8;

    auto load_stage = [&](int kc) {
        const int kb = kc * 16;
        const uint32_t base = sb + (kc & (GNSTAGE - 1)) * GSTAGE;
        {   // A: 128 rows x 16k -> 256 int4 per array
            int row = tid >> 1, kq = tid & 1;
            size_t go = (size_t)(m0 + row) * 256 + kb + kq * 8;
            uint32_t so = (uint32_t)(row * 48 + kq * 16);
            CP16(base + GA_H + so, Ahi + go);
            CP16(base + GA_L + so, Alo + go);
        }
#pragma unroll
        for (int it = 0; it < 2; ++it) {   // B: 256 rows -> 512 int4 per array
            int e = tid + it * 256;
            int row = e >> 1, kq = e & 1;
            size_t go = (size_t)(n0 + row) * 256 + kb + kq * 8;
            uint32_t so = (uint32_t)(row * 48 + kq * 16);
            CP16(base + GB_H + so, Whi + go);
            CP16(base + GB_L + so, Wlo + go);
        }
    };

#pragma unroll
    for (int s = 0; s < GNSTAGE - 1; ++s) {
        load_stage(s);
        CP_COMMIT();
    }

    for (int kc = 0; kc < 16; ++kc) {
        CP_WAIT(GNSTAGE - 2);
        __syncthreads();
        if (kc + GNSTAGE - 1 < 16) load_stage(kc + GNSTAGE - 1);
        CP_COMMIT();                        // empty commits in tail keep counts

        const uint32_t base = sb + (kc & (GNSTAGE - 1)) * GSTAGE;
        uint32_t ah[4][4], al[4][4];
#pragma unroll
        for (int mf = 0; mf < 4; ++mf) {
            uint32_t ad = base + (uint32_t)((wm + mf * 16 + arow) * 48 + kqof * 2);
            ldsm4(ah[mf], ad + GA_H);
            ldsm4(al[mf], ad + GA_L);
        }
#pragma unroll
        for (int np = 0; np < 4; ++np) {
            uint32_t bd = base + (uint32_t)((wn + np * 16 + arow) * 48 + kqof * 2);
            uint32_t bh[4], bl[4];
            ldsm4(bh, bd + GB_H);
            ldsm4(bl, bd + GB_L);
            // term 1: Ahi * Bhi (8 independent mmas)
#pragma unroll
            for (int mf = 0; mf < 4; ++mf) {
                mma16816(acc[mf][np * 2 + 0], ah[mf], bh[0], bh[2]);
                mma16816(acc[mf][np * 2 + 1], ah[mf], bh[1], bh[3]);
            }
            // term 2: Ahi * Blo
#pragma unroll
            for (int mf = 0; mf < 4; ++mf) {
                mma16816(acc[mf][np * 2 + 0], ah[mf], bl[0], bl[2]);
                mma16816(acc[mf][np * 2 + 1], ah[mf], bl[1], bl[3]);
            }
            // term 3: Alo * Bhi
#pragma unroll
            for (int mf = 0; mf < 4; ++mf) {
                mma16816(acc[mf][np * 2 + 0], al[mf], bh[0], bh[2]);
                mma16816(acc[mf][np * 2 + 1], al[mf], bh[1], bh[3]);
            }
        }
    }

    // epilogue
    const int g   = lane >> 2;
    const int tg2 = (lane & 3) * 2;
#pragma unroll
    for (int mf = 0; mf < 4; ++mf) {
        const int row = m0 + wm + mf * 16 + g;      // rows row, row+8
#pragma unroll
        for (int f = 0; f < 8; ++f) {
            const int cl = wn + (f >> 1) * 16 + (f & 1) * 8 + tg2;  // 0..255
            float bx = __ldg(&bias[n0 + cl]);
            float by = __ldg(&bias[n0 + cl + 1]);
            float v0 = acc[mf][f][0] + bx, v1 = acc[mf][f][1] + by;  // row
            float v2 = acc[mf][f][2] + bx, v3 = acc[mf][f][3] + by;  // row+8
            if (MODE == 1) {
                *(float2*)&Cext[(size_t)row * 256 + cl]       = make_float2(v0, v1);
                *(float2*)&Cext[(size_t)(row + 8) * 256 + cl] = make_float2(v2, v3);
            } else if (nsel == 0) {                 // Q: scale 1/16, split
                v0 *= 0.0625f; v1 *= 0.0625f; v2 *= 0.0625f; v3 *= 0.0625f;
                __nv_bfloat162 h, l;
                split2(v0, v1, h, l);
                *(__nv_bfloat162*)&g_qh[(size_t)row * 256 + cl] = h;
                *(__nv_bfloat162*)&g_ql[(size_t)row * 256 + cl] = l;
                split2(v2, v3, h, l);
                *(__nv_bfloat162*)&g_qh[(size_t)(row + 8) * 256 + cl] = h;
                *(__nv_bfloat162*)&g_ql[(size_t)(row + 8) * 256 + cl] = l;
            } else if (nsel == 1) {                 // K: split
                __nv_bfloat162 h, l;
                split2(v0, v1, h, l);
                *(__nv_bfloat162*)&g_kh[(size_t)row * 256 + cl] = h;
                *(__nv_bfloat162*)&g_kl[(size_t)row * 256 + cl] = l;
                split2(v2, v3, h, l);
                *(__nv_bfloat162*)&g_kh[(size_t)(row + 8) * 256 + cl] = h;
                *(__nv_bfloat162*)&g_kl[(size_t)(row + 8) * 256 + cl] = l;
            } else {                                // V: split + transpose per window
#pragma unroll
                for (int rr = 0; rr < 2; ++rr) {
                    int r  = row + rr * 8;
                    float a0 = rr ? v2 : v0, a1 = rr ? v3 : v1;
                    size_t base2 = ((size_t)(r >> 6) * 256) * 64 + (r & 63);
                    __nv_bfloat16 h0 = __float2bfloat16(a0);
                    __nv_bfloat16 h1 = __float2bfloat16(a1);
                    g_vth[base2 + (size_t)cl * 64]       = h0;
                    g_vth[base2 + (size_t)(cl + 1) * 64] = h1;
                    g_vtl[base2 + (size_t)cl * 64] =
                        __float2bfloat16(a0 - __bfloat162float(h0));
                    g_vtl[base2 + (size_t)(cl + 1) * 64] =
                        __float2bfloat16(a1 - __bfloat162float(h1));
                }
            }
        }
    }
}

// ===================== attention (mma.sync, 512 threads) =====================
// smem bytes: Qh/Ql, Kh/Kl: 64 rows x 528B; Vt h/l: 256 rows x 144B;
// P h/l: 64 rows x 144B; reductions (4 segments) + bias tables.
#define AQ_H   0
#define AQ_L   33792
#define AK_H   67584
#define AK_L   101376
#define AVT_H  135168
#define AVT_L  172032
#define AP_H   208896
#define AP_L   218112
#define A_RED  227328      // pmax[4][64] floats, psum[4][64] floats
#define A_TAB  229376      // phi[0..14] @ +0, th[0..14] @ +16 floats
#define ATTN_SMEM 229504

__global__ void __launch_bounds__(512, 1)
attn_kernel(const float* __restrict__ theta_max,
            const float* __restrict__ a_p, const float* __restrict__ b_p,
            const float* __restrict__ a_r, const float* __restrict__ b_r)
{
    extern __shared__ unsigned char sm[];
    const uint32_t sb = smem_to_u32(sm);
    float* pmax = (float*)(sm + A_RED);        // [4][64]
    float* psum = pmax + 256;                  // [4][64]
    float* tabf = (float*)(sm + A_TAB);

    const int tid  = threadIdx.x;
    const int lane = tid & 31;
    const int wid  = tid >> 5;
    const int w    = blockIdx.x;

    // async tile loads: group0 = Q,K; group1 = Vt
    {
        const int4* qh = (const int4*)(g_qh + (size_t)w * 64 * 256);
        const int4* ql = (const int4*)(g_ql + (size_t)w * 64 * 256);
        const int4* kh = (const int4*)(g_kh + (size_t)w * 64 * 256);
        const int4* kl = (const int4*)(g_kl + (size_t)w * 64 * 256);
        const int4* vh = (const int4*)(g_vth + (size_t)w * 256 * 64);
        const int4* vl = (const int4*)(g_vtl + (size_t)w * 256 * 64);
#pragma unroll
        for (int it = 0; it < 4; ++it) {
            int e = tid + it * 512;            // 0..2047
            uint32_t so = (uint32_t)((e >> 5) * 528 + (e & 31) * 16);
            CP16(sb + AQ_H + so, qh + e);
            CP16(sb + AQ_L + so, ql + e);
            CP16(sb + AK_H + so, kh + e);
            CP16(sb + AK_L + so, kl + e);
        }
        CP_COMMIT();
#pragma unroll
        for (int it = 0; it < 4; ++it) {
            int e = tid + it * 512;
            uint32_t sv = (uint32_t)((e >> 3) * 144 + (e & 7) * 16);
            CP16(sb + AVT_H + sv, vh + e);
            CP16(sb + AVT_L + sv, vl + e);
        }
        CP_COMMIT();
    }

    // bias tables: phi[dx+7] @ tabf[0..14], th[dy+7] @ tabf[16..30]
    if (tid < 15) {
        int dx = tid - 7;
        int ai = dx < 0 ? dx + 15 : dx;
        float s, c;
        sincosf((float)dx * (6.283185307179586f / 64.0f), &s, &c);
        tabf[tid] = __ldg(&a_p[ai]) * c + __ldg(&b_p[ai]) * s;
    } else if (tid >= 16 && tid < 31) {
        int dy = tid - 16 - 7;
        int ri = dy < 0 ? dy + 15 : dy;
        float tm = __ldg(&theta_max[w >> 6]);
        float s, c;
        sincosf((float)dy * (tm * 0.015625f), &s, &c);
        tabf[tid] = __ldg(&a_r[ri]) * c + __ldg(&b_r[ri]) * s;
    }

    CP_WAIT(1);                                // Q,K in smem
    __syncthreads();

    const int wm   = (wid & 3) * 16;
    const int wn2  = wid >> 2;                 // 0..3
    const int arow = (lane & 7) + ((lane >> 3) & 1) * 8;
    const int kqof = (lane >> 4) * 8;
    const int g    = lane >> 2;
    const int tg2  = (lane & 3) * 2;

    // ---- S = Q @ K^T (3-term split), warp tile 16m x 16n ----
    float accS[2][4];
#pragma unroll
    for (int f = 0; f < 2; ++f)
#pragma unroll
        for (int c = 0; c < 4; ++c) accS[f][c] = 0.0f;

#pragma unroll
    for (int kk = 0; kk < 16; ++kk) {
        const int kcol = kk * 16 + kqof;
        uint32_t aoff = (uint32_t)((wm + arow) * 528 + kcol * 2);
        uint32_t ah[4], al[4];
        ldsm4(ah, sb + AQ_H + aoff);
        ldsm4(al, sb + AQ_L + aoff);
        uint32_t boff = (uint32_t)((wn2 * 16 + arow) * 528 + kcol * 2);
        uint32_t bh[4], bl[4];
        ldsm4(bh, sb + AK_H + boff);
        ldsm4(bl, sb + AK_L + boff);
#pragma unroll
        for (int nf = 0; nf < 2; ++nf)
            mma16816(accS[nf], ah, bh[nf], bh[nf + 2]);
#pragma unroll
        for (int nf = 0; nf < 2; ++nf)
            mma16816(accS[nf], ah, bl[nf], bl[nf + 2]);
#pragma unroll
        for (int nf = 0; nf < 2; ++nf)
            mma16816(accS[nf], al, bh[nf], bh[nf + 2]);
    }

    // ---- bias + softmax (rows i0, i1; 16-wide segment per warp) ----
    const int i0 = wm + g, i1 = i0 + 8;
    float m0v = -1e30f, m1v = -1e30f;
#pragma unroll
    for (int f = 0; f < 2; ++f) {
        int jb = wn2 * 16 + f * 8 + tg2;
#pragma unroll
        for (int e = 0; e < 2; ++e) {
            int j   = jb + e;
            int dxi = (i0 & 7) - (j & 7) + 7;
            int dyi = (i0 >> 3) - (j >> 3) + 7;
            float phi = tabf[dxi];
            accS[f][e]     += phi + tabf[16 + dyi];
            accS[f][2 + e] += phi + tabf[16 + dyi + 1];
            m0v = fmaxf(m0v, accS[f][e]);
            m1v = fmaxf(m1v, accS[f][2 + e]);
        }
    }
    m0v = fmaxf(m0v, __shfl_xor_sync(0xffffffffu, m0v, 1));
    m0v = fmaxf(m0v, __shfl_xor_sync(0xffffffffu, m0v, 2));
    m1v = fmaxf(m1v, __shfl_xor_sync(0xffffffffu, m1v, 1));
    m1v = fmaxf(m1v, __shfl_xor_sync(0xffffffffu, m1v, 2));
    pmax[wn2 * 64 + i0] = m0v;
    pmax[wn2 * 64 + i1] = m1v;
    __syncthreads();
    const float mx0 = fmaxf(fmaxf(pmax[i0], pmax[64 + i0]),
                            fmaxf(pmax[128 + i0], pmax[192 + i0]));
    const float mx1 = fmaxf(fmaxf(pmax[i1], pmax[64 + i1]),
                            fmaxf(pmax[128 + i1], pmax[192 + i1]));

    float s0 = 0.0f, s1 = 0.0f;
#pragma unroll
    for (int f = 0; f < 2; ++f)
#pragma unroll
        for (int e = 0; e < 2; ++e) {
            accS[f][e]     = __expf(accS[f][e]     - mx0);
            accS[f][2 + e] = __expf(accS[f][2 + e] - mx1);
            s0 += accS[f][e];
            s1 += accS[f][2 + e];
        }
    s0 += __shfl_xor_sync(0xffffffffu, s0, 1);
    s0 += __shfl_xor_sync(0xffffffffu, s0, 2);
    s1 += __shfl_xor_sync(0xffffffffu, s1, 1);
    s1 += __shfl_xor_sync(0xffffffffu, s1, 2);
    psum[wn2 * 64 + i0] = s0;
    psum[wn2 * 64 + i1] = s1;
    __syncthreads();
    const float inv0 = 1.0f / (psum[i0] + psum[64 + i0] + psum[128 + i0] + psum[192 + i0]);
    const float inv1 = 1.0f / (psum[i1] + psum[64 + i1] + psum[128 + i1] + psum[192 + i1]);

    // store P hi/lo (bf16) to smem
#pragma unroll
    for (int f = 0; f < 2; ++f) {
        int jb = wn2 * 16 + f * 8 + tg2;
        __nv_bfloat162 h, l;
        split2(accS[f][0] * inv0, accS[f][1] * inv0, h, l);
        *(__nv_bfloat162*)(sm + AP_H + i0 * 144 + jb * 2) = h;
        *(__nv_bfloat162*)(sm + AP_L + i0 * 144 + jb * 2) = l;
        split2(accS[f][2] * inv1, accS[f][3] * inv1, h, l);
        *(__nv_bfloat162*)(sm + AP_H + i1 * 144 + jb * 2) = h;
        *(__nv_bfloat162*)(sm + AP_L + i1 * 144 + jb * 2) = l;
    }
    CP_WAIT(0);                                // Vt in smem
    __syncthreads();

    // ---- O = P @ V, warp tile 16m x 64d ----
    float accO[8][4];
#pragma unroll
    for (int f = 0; f < 8; ++f)
#pragma unroll
        for (int c = 0; c < 4; ++c) accO[f][c] = 0.0f;

#pragma unroll
    for (int kk = 0; kk < 4; ++kk) {
        const int kcol = kk * 16 + kqof;
        uint32_t aoff = (uint32_t)((wm + arow) * 144 + kcol * 2);
        uint32_t ah[4], al[4];
        ldsm4(ah, sb + AP_H + aoff);
        ldsm4(al, sb + AP_L + aoff);
#pragma unroll
        for (int np = 0; np < 4; ++np) {
            uint32_t boff = (uint32_t)((wn2 * 64 + np * 16 + arow) * 144 + kcol * 2);
            uint32_t bh[4], bl[4];
            ldsm4(bh, sb + AVT_H + boff);
            ldsm4(bl, sb + AVT_L + boff);
#pragma unroll
            for (int nf = 0; nf < 2; ++nf)
                mma16816(accO[np * 2 + nf], ah, bh[nf], bh[nf + 2]);
#pragma unroll
            for (int nf = 0; nf < 2; ++nf)
                mma16816(accO[np * 2 + nf], ah, bl[nf], bl[nf + 2]);
#pragma unroll
            for (int nf = 0; nf < 2; ++nf)
                mma16816(accO[np * 2 + nf], al, bh[nf], bh[nf + 2]);
        }
    }

    // epilogue: split O -> g_ohi/g_olo [row][256]
    const size_t r0 = (size_t)w * 64 + i0;
    const size_t r1 = (size_t)w * 64 + i1;
#pragma unroll
    for (int f = 0; f < 8; ++f) {
        int d = wn2 * 64 + (f >> 1) * 16 + (f & 1) * 8 + tg2;
        __nv_bfloat162 h, l;
        split2(accO[f][0], accO[f][1], h, l);
        *(__nv_bfloat162*)&g_ohi[r0 * 256 + d] = h;
        *(__nv_bfloat162*)&g_olo[r0 * 256 + d] = l;
        split2(accO[f][2], accO[f][3], h, l);
        *(__nv_bfloat162*)&g_ohi[r1 * 256 + d] = h;
        *(__nv_bfloat162*)&g_olo[r1 * 256 + d] = l;
    }
}

// ===================== launch ================================================
extern "C" void kernel_launch(void* const* d_in, const int* in_sizes, int n_in,
                              void* d_out, int out_size)
{
    (void)in_sizes; (void)n_in; (void)out_size;
    const float* x         = (const float*)d_in[0];
    const float* theta_max = (const float*)d_in[1];
    const float* qkv_w     = (const float*)d_in[2];
    const float* qkv_b     = (const float*)d_in[3];
    const float* proj_w    = (const float*)d_in[4];
    const float* proj_b    = (const float*)d_in[5];
    const float* a_p       = (const float*)d_in[6];
    const float* b_p       = (const float*)d_in[7];
    const float* a_r       = (const float*)d_in[8];
    const float* b_r       = (const float*)d_in[9];
    float* out = (float*)d_out;

    cudaFuncSetAttribute(gemm_mma_kernel<0>,
                         cudaFuncAttributeMaxDynamicSharedMemorySize, GEMM_SMEM);
    cudaFuncSetAttribute(gemm_mma_kernel<1>,
                         cudaFuncAttributeMaxDynamicSharedMemorySize, GEMM_SMEM);
    cudaFuncSetAttribute(attn_kernel,
                         cudaFuncAttributeMaxDynamicSharedMemorySize, ATTN_SMEM);

    split_x_kernel<<<16384, 1024>>>(x);
    split_w_kernel<<<512, 512>>>(qkv_w, proj_w);
    gemm_mma_kernel<0><<<dim3(3, 2048), 256, GEMM_SMEM>>>(qkv_b, nullptr);
    attn_kernel<<<4096, 512, ATTN_SMEM>>>(theta_max, a_p, b_p, a_r, b_r);
    gemm_mma_kernel<1><<<dim3(1, 2048), 256, GEMM_SMEM>>>(proj_b, out);
}

// round 14
// speedup vs baseline: 1.2238x; 1.1971x over previous
#include <cuda_runtime.h>
#include <cuda_bf16.h>
#include <cstdint>

// ===================== scratch (static device arrays; no allocs) ============
__device__ __nv_bfloat16  g_xhi[262144ull * 256];          // X split hi/lo
__device__ __nv_bfloat16  g_xlo[262144ull * 256];
__device__ __nv_bfloat16  g_qh[262144ull * 256];           // Q (scaled+bias) hi/lo
__device__ __nv_bfloat16  g_ql[262144ull * 256];
__device__ __nv_bfloat16  g_kh[262144ull * 256];           // K hi/lo
__device__ __nv_bfloat16  g_kl[262144ull * 256];
__device__ __nv_bfloat16  g_vth[4096ull * 256 * 64];       // V^T per window [d][j]
__device__ __nv_bfloat16  g_vtl[4096ull * 256 * 64];
__device__ __nv_bfloat16  g_ohi[262144ull * 256];          // attn out hi/lo
__device__ __nv_bfloat16  g_olo[262144ull * 256];
__device__ __nv_bfloat16  g_wqkv_hi[768 * 256];            // W^T [n][k]
__device__ __nv_bfloat16  g_wqkv_lo[768 * 256];
__device__ __nv_bfloat16  g_wproj_hi[256 * 256];
__device__ __nv_bfloat16  g_wproj_lo[256 * 256];

// ===================== helpers ==============================================
__device__ __forceinline__ uint32_t smem_to_u32(const void* p) {
    uint32_t a;
    asm("{ .reg .u64 t; cvta.to.shared.u64 t, %1; cvt.u32.u64 %0, t; }"
        : "=r"(a) : "l"(p));
    return a;
}
__device__ __forceinline__ void ldsm4(uint32_t (&r)[4], uint32_t addr) {
    asm volatile("ldmatrix.sync.aligned.m8n8.x4.shared.b16 {%0,%1,%2,%3}, [%4];"
                 : "=r"(r[0]), "=r"(r[1]), "=r"(r[2]), "=r"(r[3]) : "r"(addr));
}
__device__ __forceinline__ void mma16816(float (&d)[4], const uint32_t (&a)[4],
                                         uint32_t b0, uint32_t b1) {
    asm volatile("mma.sync.aligned.m16n8k16.row.col.f32.bf16.bf16.f32 "
                 "{%0,%1,%2,%3}, {%4,%5,%6,%7}, {%8,%9}, {%0,%1,%2,%3};"
                 : "+f"(d[0]), "+f"(d[1]), "+f"(d[2]), "+f"(d[3])
                 : "r"(a[0]), "r"(a[1]), "r"(a[2]), "r"(a[3]), "r"(b0), "r"(b1));
}
__device__ __forceinline__ void split2(float x, float y,
                                       __nv_bfloat162& h, __nv_bfloat162& l) {
    h.x = __float2bfloat16(x); h.y = __float2bfloat16(y);
    l.x = __float2bfloat16(x - __bfloat162float(h.x));
    l.y = __float2bfloat16(y - __bfloat162float(h.y));
}
#define CP16(dst, src) \
    asm volatile("cp.async.cg.shared.global [%0], [%1], 16;" \
        :: "r"((uint32_t)(dst)), "l"(__cvta_generic_to_global((const void*)(src))) : "memory")
#define CP_COMMIT() asm volatile("cp.async.commit_group;" ::: "memory")
#define CP_WAIT(n)  asm volatile("cp.async.wait_group %0;" :: "n"(n) : "memory")

// ===================== prep kernels =========================================
__global__ void __launch_bounds__(1024) split_x_kernel(const float* __restrict__ x) {
    size_t idx = (size_t)blockIdx.x * 1024 + threadIdx.x;  // float4 index
    float4 v = ((const float4*)x)[idx];
    __nv_bfloat162 h0, h1, l0, l1;
    split2(v.x, v.y, h0, l0);
    split2(v.z, v.w, h1, l1);
    ((__nv_bfloat162*)g_xhi)[idx * 2]     = h0;
    ((__nv_bfloat162*)g_xhi)[idx * 2 + 1] = h1;
    ((__nv_bfloat162*)g_xlo)[idx * 2]     = l0;
    ((__nv_bfloat162*)g_xlo)[idx * 2 + 1] = l1;
}

__global__ void __launch_bounds__(512) split_w_kernel(const float* __restrict__ qkv_w,
                                                      const float* __restrict__ proj_w) {
    int idx = blockIdx.x * 512 + threadIdx.x;
    float v; __nv_bfloat16 *ph, *pl; int off;
    if (idx < 196608) {
        int n = idx >> 8, k = idx & 255;
        v = qkv_w[k * 768 + n];
        ph = g_wqkv_hi; pl = g_wqkv_lo; off = n * 256 + k;
    } else {
        int j = idx - 196608;
        int n = j >> 8, k = j & 255;
        v = proj_w[k * 256 + n];
        ph = g_wproj_hi; pl = g_wproj_lo; off = n * 256 + k;
    }
    __nv_bfloat16 h = __float2bfloat16(v);
    ph[off] = h;
    pl[off] = __float2bfloat16(v - __bfloat162float(h));
}

// ===================== split-bf16 HMMA GEMM (cp.async 2-stage) ===============
// R10-proven design: CTA tile 128x128, 8 warps (4m x 2n), warp tile 32x64,
// k32 chunks, 2-stage cp.async, 2 CTA/SM. Only change vs R10: term-major mma
// ordering per np group (RAW distance 1 -> 4; per-acc term order preserved,
// bit-identical results).
#define T_AH 0
#define T_AL 10240
#define T_BH 20480
#define T_BL 30720
#define STAGE_BYTES 40960
#define GEMM_SMEM (2 * STAGE_BYTES)

template<int MODE>
__global__ void __launch_bounds__(256, 2)
gemm_mma_kernel(const float* __restrict__ bias, float* __restrict__ Cext)
{
    extern __shared__ unsigned char smg[];
    const __nv_bfloat16* Ahi = (MODE == 0) ? g_xhi : g_ohi;
    const __nv_bfloat16* Alo = (MODE == 0) ? g_xlo : g_olo;
    const __nv_bfloat16* Whi = (MODE == 0) ? g_wqkv_hi : g_wproj_hi;
    const __nv_bfloat16* Wlo = (MODE == 0) ? g_wqkv_lo : g_wproj_lo;

    const int tid  = threadIdx.x;
    const int lane = tid & 31;
    const int wid  = tid >> 5;
    const int m0   = blockIdx.y * 128;     // m slow: consecutive CTAs share A via L2
    const int n0   = blockIdx.x * 128;
    const int wm   = (wid & 3) * 32;
    const int wn   = (wid >> 2) * 64;
    const uint32_t sb = smem_to_u32(smg);

    float acc[2][8][4];
#pragma unroll
    for (int a = 0; a < 2; ++a)
#pragma unroll
        for (int b = 0; b < 8; ++b)
#pragma unroll
            for (int c = 0; c < 4; ++c) acc[a][b][c] = 0.0f;

    const int arow = (lane & 7) + ((lane >> 3) & 1) * 8;
    const int kqof = (lane >> 4) * 8;

    auto load_stage = [&](int kc, int s) {
        const int kb = kc * 32;
        const uint32_t base = sb + s * STAGE_BYTES;
#pragma unroll
        for (int it = 0; it < 2; ++it) {
            int e   = tid + it * 256;      // 0..511 int4 slots
            int row = e >> 2;
            int kq  = e & 3;
            size_t goffA = (size_t)(m0 + row) * 256 + kb + kq * 8;
            size_t goffB = (size_t)(n0 + row) * 256 + kb + kq * 8;
            uint32_t soff = (uint32_t)(row * 80 + kq * 16);
            CP16(base + T_AH + soff, Ahi + goffA);
            CP16(base + T_AL + soff, Alo + goffA);
            CP16(base + T_BH + soff, Whi + goffB);
            CP16(base + T_BL + soff, Wlo + goffB);
        }
    };

    load_stage(0, 0);
    CP_COMMIT();

    for (int kc = 0; kc < 8; ++kc) {
        if (kc < 7) {
            load_stage(kc + 1, (kc + 1) & 1);
            CP_COMMIT();
            CP_WAIT(1);
        } else {
            CP_WAIT(0);
        }
        __syncthreads();
        const uint32_t base = sb + (kc & 1) * STAGE_BYTES;
#pragma unroll
        for (int ks = 0; ks < 2; ++ks) {
            const int kcol = ks * 16 + kqof;
            uint32_t ah[2][4], al[2][4];
#pragma unroll
            for (int mf = 0; mf < 2; ++mf) {
                uint32_t ad = base + (uint32_t)((wm + mf * 16 + arow) * 80 + kcol * 2);
                ldsm4(ah[mf], ad + T_AH);
                ldsm4(al[mf], ad + T_AL);
            }
#pragma unroll
            for (int np = 0; np < 4; ++np) {
                uint32_t bd = base + (uint32_t)((wn + np * 16 + arow) * 80 + kcol * 2);
                uint32_t bh[4], bl[4];
                ldsm4(bh, bd + T_BH);
                ldsm4(bl, bd + T_BL);
                // term 1: Ahi * Bhi (4 independent mmas)
#pragma unroll
                for (int mf = 0; mf < 2; ++mf) {
                    mma16816(acc[mf][np * 2 + 0], ah[mf], bh[0], bh[2]);
                    mma16816(acc[mf][np * 2 + 1], ah[mf], bh[1], bh[3]);
                }
                // term 2: Ahi * Blo
#pragma unroll
                for (int mf = 0; mf < 2; ++mf) {
                    mma16816(acc[mf][np * 2 + 0], ah[mf], bl[0], bl[2]);
                    mma16816(acc[mf][np * 2 + 1], ah[mf], bl[1], bl[3]);
                }
                // term 3: Alo * Bhi
#pragma unroll
                for (int mf = 0; mf < 2; ++mf) {
                    mma16816(acc[mf][np * 2 + 0], al[mf], bh[0], bh[2]);
                    mma16816(acc[mf][np * 2 + 1], al[mf], bh[1], bh[3]);
                }
            }
        }
        __syncthreads();
    }

    // epilogue
    const int g   = lane >> 2;
    const int tg2 = (lane & 3) * 2;
#pragma unroll
    for (int mf = 0; mf < 2; ++mf) {
        const int row = m0 + wm + mf * 16 + g;      // rows row, row+8
#pragma unroll
        for (int nfi = 0; nfi < 8; ++nfi) {
            const int col = n0 + wn + nfi * 8 + tg2;
            float bx = __ldg(&bias[col]);
            float by = __ldg(&bias[col + 1]);
            float v0 = acc[mf][nfi][0] + bx, v1 = acc[mf][nfi][1] + by;  // row
            float v2 = acc[mf][nfi][2] + bx, v3 = acc[mf][nfi][3] + by;  // row+8
            if (MODE == 1) {
                *(float2*)&Cext[(size_t)row * 256 + col]       = make_float2(v0, v1);
                *(float2*)&Cext[(size_t)(row + 8) * 256 + col] = make_float2(v2, v3);
            } else if (n0 < 256) {                  // Q: scale 1/16, split
                v0 *= 0.0625f; v1 *= 0.0625f; v2 *= 0.0625f; v3 *= 0.0625f;
                __nv_bfloat162 h, l;
                split2(v0, v1, h, l);
                *(__nv_bfloat162*)&g_qh[(size_t)row * 256 + col] = h;
                *(__nv_bfloat162*)&g_ql[(size_t)row * 256 + col] = l;
                split2(v2, v3, h, l);
                *(__nv_bfloat162*)&g_qh[(size_t)(row + 8) * 256 + col] = h;
                *(__nv_bfloat162*)&g_ql[(size_t)(row + 8) * 256 + col] = l;
            } else if (n0 < 512) {                  // K: split
                int c = col - 256;
                __nv_bfloat162 h, l;
                split2(v0, v1, h, l);
                *(__nv_bfloat162*)&g_kh[(size_t)row * 256 + c] = h;
                *(__nv_bfloat162*)&g_kl[(size_t)row * 256 + c] = l;
                split2(v2, v3, h, l);
                *(__nv_bfloat162*)&g_kh[(size_t)(row + 8) * 256 + c] = h;
                *(__nv_bfloat162*)&g_kl[(size_t)(row + 8) * 256 + c] = l;
            } else {                                // V: split + transpose per window
                int d = col - 512;
#pragma unroll
                for (int rr = 0; rr < 2; ++rr) {
                    int r  = row + rr * 8;
                    float a0 = rr ? v2 : v0, a1 = rr ? v3 : v1;
                    size_t base2 = ((size_t)(r >> 6) * 256) * 64 + (r & 63);
                    __nv_bfloat16 h0 = __float2bfloat16(a0);
                    __nv_bfloat16 h1 = __float2bfloat16(a1);
                    g_vth[base2 + (size_t)d * 64]       = h0;
                    g_vth[base2 + (size_t)(d + 1) * 64] = h1;
                    g_vtl[base2 + (size_t)d * 64] =
                        __float2bfloat16(a0 - __bfloat162float(h0));
                    g_vtl[base2 + (size_t)(d + 1) * 64] =
                        __float2bfloat16(a1 - __bfloat162float(h1));
                }
            }
        }
    }
}

// ===================== attention (mma.sync, 512 threads) =====================
// smem bytes: Qh/Ql, Kh/Kl: 64 rows x 528B; Vt h/l: 256 rows x 144B;
// P h/l: 64 rows x 144B; reductions (4 segments) + bias tables.
#define AQ_H   0
#define AQ_L   33792
#define AK_H   67584
#define AK_L   101376
#define AVT_H  135168
#define AVT_L  172032
#define AP_H   208896
#define AP_L   218112
#define A_RED  227328      // pmax[4][64] floats, psum[4][64] floats
#define A_TAB  229376      // phi[0..14] @ +0, th[0..14] @ +16 floats
#define ATTN_SMEM 229504

__global__ void __launch_bounds__(512, 1)
attn_kernel(const float* __restrict__ theta_max,
            const float* __restrict__ a_p, const float* __restrict__ b_p,
            const float* __restrict__ a_r, const float* __restrict__ b_r)
{
    extern __shared__ unsigned char sm[];
    const uint32_t sb = smem_to_u32(sm);
    float* pmax = (float*)(sm + A_RED);        // [4][64]
    float* psum = pmax + 256;                  // [4][64]
    float* tabf = (float*)(sm + A_TAB);

    const int tid  = threadIdx.x;
    const int lane = tid & 31;
    const int wid  = tid >> 5;
    const int w    = blockIdx.x;

    // async tile loads: group0 = Q,K; group1 = Vt
    {
        const int4* qh = (const int4*)(g_qh + (size_t)w * 64 * 256);
        const int4* ql = (const int4*)(g_ql + (size_t)w * 64 * 256);
        const int4* kh = (const int4*)(g_kh + (size_t)w * 64 * 256);
        const int4* kl = (const int4*)(g_kl + (size_t)w * 64 * 256);
        const int4* vh = (const int4*)(g_vth + (size_t)w * 256 * 64);
        const int4* vl = (const int4*)(g_vtl + (size_t)w * 256 * 64);
#pragma unroll
        for (int it = 0; it < 4; ++it) {
            int e = tid + it * 512;            // 0..2047
            uint32_t so = (uint32_t)((e >> 5) * 528 + (e & 31) * 16);
            CP16(sb + AQ_H + so, qh + e);
            CP16(sb + AQ_L + so, ql + e);
            CP16(sb + AK_H + so, kh + e);
            CP16(sb + AK_L + so, kl + e);
        }
        CP_COMMIT();
#pragma unroll
        for (int it = 0; it < 4; ++it) {
            int e = tid + it * 512;
            uint32_t sv = (uint32_t)((e >> 3) * 144 + (e & 7) * 16);
            CP16(sb + AVT_H + sv, vh + e);
            CP16(sb + AVT_L + sv, vl + e);
        }
        CP_COMMIT();
    }

    // bias tables: phi[dx+7] @ tabf[0..14], th[dy+7] @ tabf[16..30]
    if (tid < 15) {
        int dx = tid - 7;
        int ai = dx < 0 ? dx + 15 : dx;
        float s, c;
        sincosf((float)dx * (6.283185307179586f / 64.0f), &s, &c);
        tabf[tid] = __ldg(&a_p[ai]) * c + __ldg(&b_p[ai]) * s;
    } else if (tid >= 16 && tid < 31) {
        int dy = tid - 16 - 7;
        int ri = dy < 0 ? dy + 15 : dy;
        float tm = __ldg(&theta_max[w >> 6]);
        float s, c;
        sincosf((float)dy * (tm * 0.015625f), &s, &c);
        tabf[tid] = __ldg(&a_r[ri]) * c + __ldg(&b_r[ri]) * s;
    }

    CP_WAIT(1);                                // Q,K in smem
    __syncthreads();

    const int wm   = (wid & 3) * 16;
    const int wn2  = wid >> 2;                 // 0..3
    const int arow = (lane & 7) + ((lane >> 3) & 1) * 8;
    const int kqof = (lane >> 4) * 8;
    const int g    = lane >> 2;
    const int tg2  = (lane & 3) * 2;

    // ---- S = Q @ K^T (3-term split), warp tile 16m x 16n ----
    float accS[2][4];
#pragma unroll
    for (int f = 0; f < 2; ++f)
#pragma unroll
        for (int c = 0; c < 4; ++c) accS[f][c] = 0.0f;

#pragma unroll
    for (int kk = 0; kk < 16; ++kk) {
        const int kcol = kk * 16 + kqof;
        uint32_t aoff = (uint32_t)((wm + arow) * 528 + kcol * 2);
        uint32_t ah[4], al[4];
        ldsm4(ah, sb + AQ_H + aoff);
        ldsm4(al, sb + AQ_L + aoff);
        uint32_t boff = (uint32_t)((wn2 * 16 + arow) * 528 + kcol * 2);
        uint32_t bh[4], bl[4];
        ldsm4(bh, sb + AK_H + boff);
        ldsm4(bl, sb + AK_L + boff);
#pragma unroll
        for (int nf = 0; nf < 2; ++nf)
            mma16816(accS[nf], ah, bh[nf], bh[nf + 2]);
#pragma unroll
        for (int nf = 0; nf < 2; ++nf)
            mma16816(accS[nf], ah, bl[nf], bl[nf + 2]);
#pragma unroll
        for (int nf = 0; nf < 2; ++nf)
            mma16816(accS[nf], al, bh[nf], bh[nf + 2]);
    }

    // ---- bias + softmax (rows i0, i1; 16-wide segment per warp) ----
    const int i0 = wm + g, i1 = i0 + 8;
    float m0v = -1e30f, m1v = -1e30f;
#pragma unroll
    for (int f = 0; f < 2; ++f) {
        int jb = wn2 * 16 + f * 8 + tg2;
#pragma unroll
        for (int e = 0; e < 2; ++e) {
            int j   = jb + e;
            int dxi = (i0 & 7) - (j & 7) + 7;
            int dyi = (i0 >> 3) - (j >> 3) + 7;
            float phi = tabf[dxi];
            accS[f][e]     += phi + tabf[16 + dyi];
            accS[f][2 + e] += phi + tabf[16 + dyi + 1];
            m0v = fmaxf(m0v, accS[f][e]);
            m1v = fmaxf(m1v, accS[f][2 + e]);
        }
    }
    m0v = fmaxf(m0v, __shfl_xor_sync(0xffffffffu, m0v, 1));
    m0v = fmaxf(m0v, __shfl_xor_sync(0xffffffffu, m0v, 2));
    m1v = fmaxf(m1v, __shfl_xor_sync(0xffffffffu, m1v, 1));
    m1v = fmaxf(m1v, __shfl_xor_sync(0xffffffffu, m1v, 2));
    pmax[wn2 * 64 + i0] = m0v;
    pmax[wn2 * 64 + i1] = m1v;
    __syncthreads();
    const float mx0 = fmaxf(fmaxf(pmax[i0], pmax[64 + i0]),
                            fmaxf(pmax[128 + i0], pmax[192 + i0]));
    const float mx1 = fmaxf(fmaxf(pmax[i1], pmax[64 + i1]),
                            fmaxf(pmax[128 + i1], pmax[192 + i1]));

    float s0 = 0.0f, s1 = 0.0f;
#pragma unroll
    for (int f = 0; f < 2; ++f)
#pragma unroll
        for (int e = 0; e < 2; ++e) {
            accS[f][e]     = __expf(accS[f][e]     - mx0);
            accS[f][2 + e] = __expf(accS[f][2 + e] - mx1);
            s0 += accS[f][e];
            s1 += accS[f][2 + e];
        }
    s0 += __shfl_xor_sync(0xffffffffu, s0, 1);
    s0 += __shfl_xor_sync(0xffffffffu, s0, 2);
    s1 += __shfl_xor_sync(0xffffffffu, s1, 1);
    s1 += __shfl_xor_sync(0xffffffffu, s1, 2);
    psum[wn2 * 64 + i0] = s0;
    psum[wn2 * 64 + i1] = s1;
    __syncthreads();
    const float inv0 = 1.0f / (psum[i0] + psum[64 + i0] + psum[128 + i0] + psum[192 + i0]);
    const float inv1 = 1.0f / (psum[i1] + psum[64 + i1] + psum[128 + i1] + psum[192 + i1]);

    // store P hi/lo (bf16) to smem
#pragma unroll
    for (int f = 0; f < 2; ++f) {
        int jb = wn2 * 16 + f * 8 + tg2;
        __nv_bfloat162 h, l;
        split2(accS[f][0] * inv0, accS[f][1] * inv0, h, l);
        *(__nv_bfloat162*)(sm + AP_H + i0 * 144 + jb * 2) = h;
        *(__nv_bfloat162*)(sm + AP_L + i0 * 144 + jb * 2) = l;
        split2(accS[f][2] * inv1, accS[f][3] * inv1, h, l);
        *(__nv_bfloat162*)(sm + AP_H + i1 * 144 + jb * 2) = h;
        *(__nv_bfloat162*)(sm + AP_L + i1 * 144 + jb * 2) = l;
    }
    CP_WAIT(0);                                // Vt in smem
    __syncthreads();

    // ---- O = P @ V, warp tile 16m x 64d ----
    float accO[8][4];
#pragma unroll
    for (int f = 0; f < 8; ++f)
#pragma unroll
        for (int c = 0; c < 4; ++c) accO[f][c] = 0.0f;

#pragma unroll
    for (int kk = 0; kk < 4; ++kk) {
        const int kcol = kk * 16 + kqof;
        uint32_t aoff = (uint32_t)((wm + arow) * 144 + kcol * 2);
        uint32_t ah[4], al[4];
        ldsm4(ah, sb + AP_H + aoff);
        ldsm4(al, sb + AP_L + aoff);
#pragma unroll
        for (int np = 0; np < 4; ++np) {
            uint32_t boff = (uint32_t)((wn2 * 64 + np * 16 + arow) * 144 + kcol * 2);
            uint32_t bh[4], bl[4];
            ldsm4(bh, sb + AVT_H + boff);
            ldsm4(bl, sb + AVT_L + boff);
#pragma unroll
            for (int nf = 0; nf < 2; ++nf)
                mma16816(accO[np * 2 + nf], ah, bh[nf], bh[nf + 2]);
#pragma unroll
            for (int nf = 0; nf < 2; ++nf)
                mma16816(accO[np * 2 + nf], ah, bl[nf], bl[nf + 2]);
#pragma unroll
            for (int nf = 0; nf < 2; ++nf)
                mma16816(accO[np * 2 + nf], al, bh[nf], bh[nf + 2]);
        }
    }

    // epilogue: split O -> g_ohi/g_olo [row][256]
    const size_t r0 = (size_t)w * 64 + i0;
    const size_t r1 = (size_t)w * 64 + i1;
#pragma unroll
    for (int f = 0; f < 8; ++f) {
        int d = wn2 * 64 + (f >> 1) * 16 + (f & 1) * 8 + tg2;
        __nv_bfloat162 h, l;
        split2(accO[f][0], accO[f][1], h, l);
        *(__nv_bfloat162*)&g_ohi[r0 * 256 + d] = h;
        *(__nv_bfloat162*)&g_olo[r0 * 256 + d] = l;
        split2(accO[f][2], accO[f][3], h, l);
        *(__nv_bfloat162*)&g_ohi[r1 * 256 + d] = h;
        *(__nv_bfloat162*)&g_olo[r1 * 256 + d] = l;
    }
}

// ===================== launch ================================================
extern "C" void kernel_launch(void* const* d_in, const int* in_sizes, int n_in,
                              void* d_out, int out_size)
{
    (void)in_sizes; (void)n_in; (void)out_size;
    const float* x         = (const float*)d_in[0];
    const float* theta_max = (const float*)d_in[1];
    const float* qkv_w     = (const float*)d_in[2];
    const float* qkv_b     = (const float*)d_in[3];
    const float* proj_w    = (const float*)d_in[4];
    const float* proj_b    = (const float*)d_in[5];
    const float* a_p       = (const float*)d_in[6];
    const float* b_p       = (const float*)d_in[7];
    const float* a_r       = (const float*)d_in[8];
    const float* b_r       = (const float*)d_in[9];
    float* out = (float*)d_out;

    cudaFuncSetAttribute(gemm_mma_kernel<0>,
                         cudaFuncAttributeMaxDynamicSharedMemorySize, GEMM_SMEM);
    cudaFuncSetAttribute(gemm_mma_kernel<1>,
                         cudaFuncAttributeMaxDynamicSharedMemorySize, GEMM_SMEM);
    cudaFuncSetAttribute(attn_kernel,
                         cudaFuncAttributeMaxDynamicSharedMemorySize, ATTN_SMEM);

    split_x_kernel<<<16384, 1024>>>(x);
    split_w_kernel<<<512, 512>>>(qkv_w, proj_w);
    gemm_mma_kernel<0><<<dim3(6, 2048), 256, GEMM_SMEM>>>(qkv_b, nullptr);
    attn_kernel<<<4096, 512, ATTN_SMEM>>>(theta_max, a_p, b_p, a_r, b_r);
    gemm_mma_kernel<1><<<dim3(2, 2048), 256, GEMM_SMEM>>>(proj_b, out);
}

// round 16
// speedup vs baseline: 1.2253x; 1.0012x over previous
#include <cuda_runtime.h>
#include <cuda_bf16.h>
#include <cstdint>

// ===================== scratch (static device arrays; no allocs) ============
__device__ __nv_bfloat16  g_xhi[262144ull * 256];          // X split hi/lo
__device__ __nv_bfloat16  g_xlo[262144ull * 256];
__device__ __nv_bfloat16  g_qh[262144ull * 256];           // Q (scaled+bias) hi/lo
__device__ __nv_bfloat16  g_ql[262144ull * 256];
__device__ __nv_bfloat16  g_kh[262144ull * 256];           // K hi/lo
__device__ __nv_bfloat16  g_kl[262144ull * 256];
__device__ __nv_bfloat16  g_vth[4096ull * 256 * 64];       // V^T per window [d][j]
__device__ __nv_bfloat16  g_vtl[4096ull * 256 * 64];
__device__ __nv_bfloat16  g_ohi[262144ull * 256];          // attn out hi/lo
__device__ __nv_bfloat16  g_olo[262144ull * 256];
__device__ __nv_bfloat16  g_wqkv_hi[768 * 256];            // W^T [n][k]
__device__ __nv_bfloat16  g_wqkv_lo[768 * 256];
__device__ __nv_bfloat16  g_wproj_hi[256 * 256];
__device__ __nv_bfloat16  g_wproj_lo[256 * 256];

// ===================== helpers ==============================================
__device__ __forceinline__ uint32_t smem_to_u32(const void* p) {
    uint32_t a;
    asm("{ .reg .u64 t; cvta.to.shared.u64 t, %1; cvt.u32.u64 %0, t; }"
        : "=r"(a) : "l"(p));
    return a;
}
__device__ __forceinline__ void ldsm4(uint32_t (&r)[4], uint32_t addr) {
    asm volatile("ldmatrix.sync.aligned.m8n8.x4.shared.b16 {%0,%1,%2,%3}, [%4];"
                 : "=r"(r[0]), "=r"(r[1]), "=r"(r[2]), "=r"(r[3]) : "r"(addr));
}
__device__ __forceinline__ void mma16816(float (&d)[4], const uint32_t (&a)[4],
                                         uint32_t b0, uint32_t b1) {
    asm volatile("mma.sync.aligned.m16n8k16.row.col.f32.bf16.bf16.f32 "
                 "{%0,%1,%2,%3}, {%4,%5,%6,%7}, {%8,%9}, {%0,%1,%2,%3};"
                 : "+f"(d[0]), "+f"(d[1]), "+f"(d[2]), "+f"(d[3])
                 : "r"(a[0]), "r"(a[1]), "r"(a[2]), "r"(a[3]), "r"(b0), "r"(b1));
}
__device__ __forceinline__ void split2(float x, float y,
                                       __nv_bfloat162& h, __nv_bfloat162& l) {
    h.x = __float2bfloat16(x); h.y = __float2bfloat16(y);
    l.x = __float2bfloat16(x - __bfloat162float(h.x));
    l.y = __float2bfloat16(y - __bfloat162float(h.y));
}
#define CP16(dst, src) \
    asm volatile("cp.async.cg.shared.global [%0], [%1], 16;" \
        :: "r"((uint32_t)(dst)), "l"(__cvta_generic_to_global((const void*)(src))) : "memory")
#define CP_COMMIT() asm volatile("cp.async.commit_group;" ::: "memory")
#define CP_WAIT(n)  asm volatile("cp.async.wait_group %0;" :: "n"(n) : "memory")

// ===================== prep kernels =========================================
__global__ void __launch_bounds__(1024) split_x_kernel(const float* __restrict__ x) {
    size_t idx = (size_t)blockIdx.x * 1024 + threadIdx.x;  // float4 index
    float4 v = ((const float4*)x)[idx];
    __nv_bfloat162 h0, h1, l0, l1;
    split2(v.x, v.y, h0, l0);
    split2(v.z, v.w, h1, l1);
    ((__nv_bfloat162*)g_xhi)[idx * 2]     = h0;
    ((__nv_bfloat162*)g_xhi)[idx * 2 + 1] = h1;
    ((__nv_bfloat162*)g_xlo)[idx * 2]     = l0;
    ((__nv_bfloat162*)g_xlo)[idx * 2 + 1] = l1;
}

__global__ void __launch_bounds__(512) split_w_kernel(const float* __restrict__ qkv_w,
                                                      const float* __restrict__ proj_w) {
    int idx = blockIdx.x * 512 + threadIdx.x;
    float v; __nv_bfloat16 *ph, *pl; int off;
    if (idx < 196608) {
        int n = idx >> 8, k = idx & 255;
        v = qkv_w[k * 768 + n];
        ph = g_wqkv_hi; pl = g_wqkv_lo; off = n * 256 + k;
    } else {
        int j = idx - 196608;
        int n = j >> 8, k = j & 255;
        v = proj_w[k * 256 + n];
        ph = g_wproj_hi; pl = g_wproj_lo; off = n * 256 + k;
    }
    __nv_bfloat16 h = __float2bfloat16(v);
    ph[off] = h;
    pl[off] = __float2bfloat16(v - __bfloat162float(h));
}

// ===================== split-bf16 HMMA GEMM (cp.async 2-stage) ===============
// R10-proven design: CTA tile 128x128, 8 warps (4m x 2n), warp tile 32x64,
// k32 chunks, 2-stage cp.async, 2 CTA/SM. Only change vs R10: term-major mma
// ordering per np group (RAW distance 1 -> 4; per-acc term order preserved,
// bit-identical results).
#define T_AH 0
#define T_AL 10240
#define T_BH 20480
#define T_BL 30720
#define STAGE_BYTES 40960
#define GEMM_SMEM (2 * STAGE_BYTES)

template<int MODE>
__global__ void __launch_bounds__(256, 2)
gemm_mma_kernel(const float* __restrict__ bias, float* __restrict__ Cext)
{
    extern __shared__ unsigned char smg[];
    const __nv_bfloat16* Ahi = (MODE == 0) ? g_xhi : g_ohi;
    const __nv_bfloat16* Alo = (MODE == 0) ? g_xlo : g_olo;
    const __nv_bfloat16* Whi = (MODE == 0) ? g_wqkv_hi : g_wproj_hi;
    const __nv_bfloat16* Wlo = (MODE == 0) ? g_wqkv_lo : g_wproj_lo;

    const int tid  = threadIdx.x;
    const int lane = tid & 31;
    const int wid  = tid >> 5;
    const int m0   = blockIdx.y * 128;     // m slow: consecutive CTAs share A via L2
    const int n0   = blockIdx.x * 128;
    const int wm   = (wid & 3) * 32;
    const int wn   = (wid >> 2) * 64;
    const uint32_t sb = smem_to_u32(smg);

    float acc[2][8][4];
#pragma unroll
    for (int a = 0; a < 2; ++a)
#pragma unroll
        for (int b = 0; b < 8; ++b)
#pragma unroll
            for (int c = 0; c < 4; ++c) acc[a][b][c] = 0.0f;

    const int arow = (lane & 7) + ((lane >> 3) & 1) * 8;
    const int kqof = (lane >> 4) * 8;

    auto load_stage = [&](int kc, int s) {
        const int kb = kc * 32;
        const uint32_t base = sb + s * STAGE_BYTES;
#pragma unroll
        for (int it = 0; it < 2; ++it) {
            int e   = tid + it * 256;      // 0..511 int4 slots
            int row = e >> 2;
            int kq  = e & 3;
            size_t goffA = (size_t)(m0 + row) * 256 + kb + kq * 8;
            size_t goffB = (size_t)(n0 + row) * 256 + kb + kq * 8;
            uint32_t soff = (uint32_t)(row * 80 + kq * 16);
            CP16(base + T_AH + soff, Ahi + goffA);
            CP16(base + T_AL + soff, Alo + goffA);
            CP16(base + T_BH + soff, Whi + goffB);
            CP16(base + T_BL + soff, Wlo + goffB);
        }
    };

    load_stage(0, 0);
    CP_COMMIT();

    for (int kc = 0; kc < 8; ++kc) {
        if (kc < 7) {
            load_stage(kc + 1, (kc + 1) & 1);
            CP_COMMIT();
            CP_WAIT(1);
        } else {
            CP_WAIT(0);
        }
        __syncthreads();
        const uint32_t base = sb + (kc & 1) * STAGE_BYTES;
#pragma unroll
        for (int ks = 0; ks < 2; ++ks) {
            const int kcol = ks * 16 + kqof;
            uint32_t ah[2][4], al[2][4];
#pragma unroll
            for (int mf = 0; mf < 2; ++mf) {
                uint32_t ad = base + (uint32_t)((wm + mf * 16 + arow) * 80 + kcol * 2);
                ldsm4(ah[mf], ad + T_AH);
                ldsm4(al[mf], ad + T_AL);
            }
#pragma unroll
            for (int np = 0; np < 4; ++np) {
                uint32_t bd = base + (uint32_t)((wn + np * 16 + arow) * 80 + kcol * 2);
                uint32_t bh[4], bl[4];
                ldsm4(bh, bd + T_BH);
                ldsm4(bl, bd + T_BL);
                // term 1: Ahi * Bhi (4 independent mmas)
#pragma unroll
                for (int mf = 0; mf < 2; ++mf) {
                    mma16816(acc[mf][np * 2 + 0], ah[mf], bh[0], bh[2]);
                    mma16816(acc[mf][np * 2 + 1], ah[mf], bh[1], bh[3]);
                }
                // term 2: Ahi * Blo
#pragma unroll
                for (int mf = 0; mf < 2; ++mf) {
                    mma16816(acc[mf][np * 2 + 0], ah[mf], bl[0], bl[2]);
                    mma16816(acc[mf][np * 2 + 1], ah[mf], bl[1], bl[3]);
                }
                // term 3: Alo * Bhi
#pragma unroll
                for (int mf = 0; mf < 2; ++mf) {
                    mma16816(acc[mf][np * 2 + 0], al[mf], bh[0], bh[2]);
                    mma16816(acc[mf][np * 2 + 1], al[mf], bh[1], bh[3]);
                }
            }
        }
        __syncthreads();
    }

    // epilogue
    const int g   = lane >> 2;
    const int tg2 = (lane & 3) * 2;
#pragma unroll
    for (int mf = 0; mf < 2; ++mf) {
        const int row = m0 + wm + mf * 16 + g;      // rows row, row+8
#pragma unroll
        for (int nfi = 0; nfi < 8; ++nfi) {
            const int col = n0 + wn + nfi * 8 + tg2;
            float bx = __ldg(&bias[col]);
            float by = __ldg(&bias[col + 1]);
            float v0 = acc[mf][nfi][0] + bx, v1 = acc[mf][nfi][1] + by;  // row
            float v2 = acc[mf][nfi][2] + bx, v3 = acc[mf][nfi][3] + by;  // row+8
            if (MODE == 1) {
                *(float2*)&Cext[(size_t)row * 256 + col]       = make_float2(v0, v1);
                *(float2*)&Cext[(size_t)(row + 8) * 256 + col] = make_float2(v2, v3);
            } else if (n0 < 256) {                  // Q: scale 1/16, split
                v0 *= 0.0625f; v1 *= 0.0625f; v2 *= 0.0625f; v3 *= 0.0625f;
                __nv_bfloat162 h, l;
                split2(v0, v1, h, l);
                *(__nv_bfloat162*)&g_qh[(size_t)row * 256 + col] = h;
                *(__nv_bfloat162*)&g_ql[(size_t)row * 256 + col] = l;
                split2(v2, v3, h, l);
                *(__nv_bfloat162*)&g_qh[(size_t)(row + 8) * 256 + col] = h;
                *(__nv_bfloat162*)&g_ql[(size_t)(row + 8) * 256 + col] = l;
            } else if (n0 < 512) {                  // K: split
                int c = col - 256;
                __nv_bfloat162 h, l;
                split2(v0, v1, h, l);
                *(__nv_bfloat162*)&g_kh[(size_t)row * 256 + c] = h;
                *(__nv_bfloat162*)&g_kl[(size_t)row * 256 + c] = l;
                split2(v2, v3, h, l);
                *(__nv_bfloat162*)&g_kh[(size_t)(row + 8) * 256 + c] = h;
                *(__nv_bfloat162*)&g_kl[(size_t)(row + 8) * 256 + c] = l;
            } else {                                // V: split + transpose per window
                int d = col - 512;
#pragma unroll
                for (int rr = 0; rr < 2; ++rr) {
                    int r  = row + rr * 8;
                    float a0 = rr ? v2 : v0, a1 = rr ? v3 : v1;
                    size_t base2 = ((size_t)(r >> 6) * 256) * 64 + (r & 63);
                    __nv_bfloat16 h0 = __float2bfloat16(a0);
                    __nv_bfloat16 h1 = __float2bfloat16(a1);
                    g_vth[base2 + (size_t)d * 64]       = h0;
                    g_vth[base2 + (size_t)(d + 1) * 64] = h1;
                    g_vtl[base2 + (size_t)d * 64] =
                        __float2bfloat16(a0 - __bfloat162float(h0));
                    g_vtl[base2 + (size_t)(d + 1) * 64] =
                        __float2bfloat16(a1 - __bfloat162float(h1));
                }
            }
        }
    }
}

// ===================== attention (mma.sync, 512 threads) =====================
// smem bytes: Qh/Ql, Kh/Kl: 64 rows x 528B; Vt h/l: 256 rows x 144B;
// P h/l: 64 rows x 144B; reductions (4 segments) + bias tables.
#define AQ_H   0
#define AQ_L   33792
#define AK_H   67584
#define AK_L   101376
#define AVT_H  135168
#define AVT_L  172032
#define AP_H   208896
#define AP_L   218112
#define A_RED  227328      // pmax[4][64] floats, psum[4][64] floats
#define A_TAB  229376      // phi[0..14] @ +0, th[0..14] @ +16 floats
#define ATTN_SMEM 229504

__global__ void __launch_bounds__(512, 1)
attn_kernel(const float* __restrict__ theta_max,
            const float* __restrict__ a_p, const float* __restrict__ b_p,
            const float* __restrict__ a_r, const float* __restrict__ b_r)
{
    extern __shared__ unsigned char sm[];
    const uint32_t sb = smem_to_u32(sm);
    float* pmax = (float*)(sm + A_RED);        // [4][64]
    float* psum = pmax + 256;                  // [4][64]
    float* tabf = (float*)(sm + A_TAB);

    const int tid  = threadIdx.x;
    const int lane = tid & 31;
    const int wid  = tid >> 5;
    const int w    = blockIdx.x;

    // async tile loads: group0 = Q,K; group1 = Vt
    {
        const int4* qh = (const int4*)(g_qh + (size_t)w * 64 * 256);
        const int4* ql = (const int4*)(g_ql + (size_t)w * 64 * 256);
        const int4* kh = (const int4*)(g_kh + (size_t)w * 64 * 256);
        const int4* kl = (const int4*)(g_kl + (size_t)w * 64 * 256);
        const int4* vh = (const int4*)(g_vth + (size_t)w * 256 * 64);
        const int4* vl = (const int4*)(g_vtl + (size_t)w * 256 * 64);
#pragma unroll
        for (int it = 0; it < 4; ++it) {
            int e = tid + it * 512;            // 0..2047
            uint32_t so = (uint32_t)((e >> 5) * 528 + (e & 31) * 16);
            CP16(sb + AQ_H + so, qh + e);
            CP16(sb + AQ_L + so, ql + e);
            CP16(sb + AK_H + so, kh + e);
            CP16(sb + AK_L + so, kl + e);
        }
        CP_COMMIT();
#pragma unroll
        for (int it = 0; it < 4; ++it) {
            int e = tid + it * 512;
            uint32_t sv = (uint32_t)((e >> 3) * 144 + (e & 7) * 16);
            CP16(sb + AVT_H + sv, vh + e);
            CP16(sb + AVT_L + sv, vl + e);
        }
        CP_COMMIT();
    }

    // bias tables: phi[dx+7] @ tabf[0..14], th[dy+7] @ tabf[16..30]
    if (tid < 15) {
        int dx = tid - 7;
        int ai = dx < 0 ? dx + 15 : dx;
        float s, c;
        sincosf((float)dx * (6.283185307179586f / 64.0f), &s, &c);
        tabf[tid] = __ldg(&a_p[ai]) * c + __ldg(&b_p[ai]) * s;
    } else if (tid >= 16 && tid < 31) {
        int dy = tid - 16 - 7;
        int ri = dy < 0 ? dy + 15 : dy;
        float tm = __ldg(&theta_max[w >> 6]);
        float s, c;
        sincosf((float)dy * (tm * 0.015625f), &s, &c);
        tabf[tid] = __ldg(&a_r[ri]) * c + __ldg(&b_r[ri]) * s;
    }

    CP_WAIT(1);                                // Q,K in smem
    __syncthreads();

    const int wm   = (wid & 3) * 16;
    const int wn2  = wid >> 2;                 // 0..3
    const int arow = (lane & 7) + ((lane >> 3) & 1) * 8;
    const int kqof = (lane >> 4) * 8;
    const int g    = lane >> 2;
    const int tg2  = (lane & 3) * 2;

    // ---- S = Q @ K^T (3-term split), warp tile 16m x 16n ----
    float accS[2][4];
#pragma unroll
    for (int f = 0; f < 2; ++f)
#pragma unroll
        for (int c = 0; c < 4; ++c) accS[f][c] = 0.0f;

#pragma unroll
    for (int kk = 0; kk < 16; ++kk) {
        const int kcol = kk * 16 + kqof;
        uint32_t aoff = (uint32_t)((wm + arow) * 528 + kcol * 2);
        uint32_t ah[4], al[4];
        ldsm4(ah, sb + AQ_H + aoff);
        ldsm4(al, sb + AQ_L + aoff);
        uint32_t boff = (uint32_t)((wn2 * 16 + arow) * 528 + kcol * 2);
        uint32_t bh[4], bl[4];
        ldsm4(bh, sb + AK_H + boff);
        ldsm4(bl, sb + AK_L + boff);
#pragma unroll
        for (int nf = 0; nf < 2; ++nf)
            mma16816(accS[nf], ah, bh[nf], bh[nf + 2]);
#pragma unroll
        for (int nf = 0; nf < 2; ++nf)
            mma16816(accS[nf], ah, bl[nf], bl[nf + 2]);
#pragma unroll
        for (int nf = 0; nf < 2; ++nf)
            mma16816(accS[nf], al, bh[nf], bh[nf + 2]);
    }

    // ---- bias + softmax (rows i0, i1; 16-wide segment per warp) ----
    const int i0 = wm + g, i1 = i0 + 8;
    float m0v = -1e30f, m1v = -1e30f;
#pragma unroll
    for (int f = 0; f < 2; ++f) {
        int jb = wn2 * 16 + f * 8 + tg2;
#pragma unroll
        for (int e = 0; e < 2; ++e) {
            int j   = jb + e;
            int dxi = (i0 & 7) - (j & 7) + 7;
            int dyi = (i0 >> 3) - (j >> 3) + 7;
            float phi = tabf[dxi];
            accS[f][e]     += phi + tabf[16 + dyi];
            accS[f][2 + e] += phi + tabf[16 + dyi + 1];
            m0v = fmaxf(m0v, accS[f][e]);
            m1v = fmaxf(m1v, accS[f][2 + e]);
        }
    }
    m0v = fmaxf(m0v, __shfl_xor_sync(0xffffffffu, m0v, 1));
    m0v = fmaxf(m0v, __shfl_xor_sync(0xffffffffu, m0v, 2));
    m1v = fmaxf(m1v, __shfl_xor_sync(0xffffffffu, m1v, 1));
    m1v = fmaxf(m1v, __shfl_xor_sync(0xffffffffu, m1v, 2));
    pmax[wn2 * 64 + i0] = m0v;
    pmax[wn2 * 64 + i1] = m1v;
    __syncthreads();
    const float mx0 = fmaxf(fmaxf(pmax[i0], pmax[64 + i0]),
                            fmaxf(pmax[128 + i0], pmax[192 + i0]));
    const float mx1 = fmaxf(fmaxf(pmax[i1], pmax[64 + i1]),
                            fmaxf(pmax[128 + i1], pmax[192 + i1]));

    float s0 = 0.0f, s1 = 0.0f;
#pragma unroll
    for (int f = 0; f < 2; ++f)
#pragma unroll
        for (int e = 0; e < 2; ++e) {
            accS[f][e]     = __expf(accS[f][e]     - mx0);
            accS[f][2 + e] = __expf(accS[f][2 + e] - mx1);
            s0 += accS[f][e];
            s1 += accS[f][2 + e];
        }
    s0 += __shfl_xor_sync(0xffffffffu, s0, 1);
    s0 += __shfl_xor_sync(0xffffffffu, s0, 2);
    s1 += __shfl_xor_sync(0xffffffffu, s1, 1);
    s1 += __shfl_xor_sync(0xffffffffu, s1, 2);
    psum[wn2 * 64 + i0] = s0;
    psum[wn2 * 64 + i1] = s1;
    __syncthreads();
    const float inv0 = 1.0f / (psum[i0] + psum[64 + i0] + psum[128 + i0] + psum[192 + i0]);
    const float inv1 = 1.0f / (psum[i1] + psum[64 + i1] + psum[128 + i1] + psum[192 + i1]);

    // store P hi/lo (bf16) to smem
#pragma unroll
    for (int f = 0; f < 2; ++f) {
        int jb = wn2 * 16 + f * 8 + tg2;
        __nv_bfloat162 h, l;
        split2(accS[f][0] * inv0, accS[f][1] * inv0, h, l);
        *(__nv_bfloat162*)(sm + AP_H + i0 * 144 + jb * 2) = h;
        *(__nv_bfloat162*)(sm + AP_L + i0 * 144 + jb * 2) = l;
        split2(accS[f][2] * inv1, accS[f][3] * inv1, h, l);
        *(__nv_bfloat162*)(sm + AP_H + i1 * 144 + jb * 2) = h;
        *(__nv_bfloat162*)(sm + AP_L + i1 * 144 + jb * 2) = l;
    }
    CP_WAIT(0);                                // Vt in smem
    __syncthreads();

    // ---- O = P @ V, warp tile 16m x 64d ----
    float accO[8][4];
#pragma unroll
    for (int f = 0; f < 8; ++f)
#pragma unroll
        for (int c = 0; c < 4; ++c) accO[f][c] = 0.0f;

#pragma unroll
    for (int kk = 0; kk < 4; ++kk) {
        const int kcol = kk * 16 + kqof;
        uint32_t aoff = (uint32_t)((wm + arow) * 144 + kcol * 2);
        uint32_t ah[4], al[4];
        ldsm4(ah, sb + AP_H + aoff);
        ldsm4(al, sb + AP_L + aoff);
#pragma unroll
        for (int np = 0; np < 4; ++np) {
            uint32_t boff = (uint32_t)((wn2 * 64 + np * 16 + arow) * 144 + kcol * 2);
            uint32_t bh[4], bl[4];
            ldsm4(bh, sb + AVT_H + boff);
            ldsm4(bl, sb + AVT_L + boff);
#pragma unroll
            for (int nf = 0; nf < 2; ++nf)
                mma16816(accO[np * 2 + nf], ah, bh[nf], bh[nf + 2]);
#pragma unroll
            for (int nf = 0; nf < 2; ++nf)
                mma16816(accO[np * 2 + nf], ah, bl[nf], bl[nf + 2]);
#pragma unroll
            for (int nf = 0; nf < 2; ++nf)
                mma16816(accO[np * 2 + nf], al, bh[nf], bh[nf + 2]);
        }
    }

    // epilogue: split O -> g_ohi/g_olo [row][256]
    const size_t r0 = (size_t)w * 64 + i0;
    const size_t r1 = (size_t)w * 64 + i1;
#pragma unroll
    for (int f = 0; f < 8; ++f) {
        int d = wn2 * 64 + (f >> 1) * 16 + (f & 1) * 8 + tg2;
        __nv_bfloat162 h, l;
        split2(accO[f][0], accO[f][1], h, l);
        *(__nv_bfloat162*)&g_ohi[r0 * 256 + d] = h;
        *(__nv_bfloat162*)&g_olo[r0 * 256 + d] = l;
        split2(accO[f][2], accO[f][3], h, l);
        *(__nv_bfloat162*)&g_ohi[r1 * 256 + d] = h;
        *(__nv_bfloat162*)&g_olo[r1 * 256 + d] = l;
    }
}

// ===================== launch ================================================
extern "C" void kernel_launch(void* const* d_in, const int* in_sizes, int n_in,
                              void* d_out, int out_size)
{
    (void)in_sizes; (void)n_in; (void)out_size;
    const float* x         = (const float*)d_in[0];
    const float* theta_max = (const float*)d_in[1];
    const float* qkv_w     = (const float*)d_in[2];
    const float* qkv_b     = (const float*)d_in[3];
    const float* proj_w    = (const float*)d_in[4];
    const float* proj_b    = (const float*)d_in[5];
    const float* a_p       = (const float*)d_in[6];
    const float* b_p       = (const float*)d_in[7];
    const float* a_r       = (const float*)d_in[8];
    const float* b_r       = (const float*)d_in[9];
    float* out = (float*)d_out;

    cudaFuncSetAttribute(gemm_mma_kernel<0>,
                         cudaFuncAttributeMaxDynamicSharedMemorySize, GEMM_SMEM);
    cudaFuncSetAttribute(gemm_mma_kernel<1>,
                         cudaFuncAttributeMaxDynamicSharedMemorySize, GEMM_SMEM);
    cudaFuncSetAttribute(attn_kernel,
                         cudaFuncAttributeMaxDynamicSharedMemorySize, ATTN_SMEM);

    split_x_kernel<<<16384, 1024>>>(x);
    split_w_kernel<<<512, 512>>>(qkv_w, proj_w);
    gemm_mma_kernel<0><<<dim3(6, 2048), 256, GEMM_SMEM>>>(qkv_b, nullptr);
    attn_kernel<<<4096, 512, ATTN_SMEM>>>(theta_max, a_p, b_p, a_r, b_r);
    gemm_mma_kernel<1><<<dim3(2, 2048), 256, GEMM_SMEM>>>(proj_b, out);
}